// round 12
// baseline (speedup 1.0000x reference)
#include <cuda_runtime.h>
#include <cuda_bf16.h>
#include <math.h>
#include <stdint.h>

#define BATCH 2
#define SEQ   2048
#define DMODEL 1024
#define NHEAD 16
#define HDIM  64
#define ROWS  (BATCH*SEQ)          // 4096
#define QKV_N (3*DMODEL)           // 3072

typedef __nv_bfloat16 bf;

// ---------------------------------------------------------------------------
// Device scratch
// ---------------------------------------------------------------------------
__device__ bf g_xhi[(size_t)ROWS * DMODEL];
__device__ bf g_xlo[(size_t)ROWS * DMODEL];
__device__ bf g_wqh[(size_t)QKV_N * DMODEL];   // W_qkv^T [3072][1024]
__device__ bf g_wql[(size_t)QKV_N * DMODEL];
__device__ bf g_woh[(size_t)DMODEL * DMODEL];  // W_out^T [1024][1024]
__device__ bf g_wol[(size_t)DMODEL * DMODEL];
__device__ bf g_chi[(size_t)ROWS * DMODEL];    // ctx hi/lo [row][1024]
__device__ bf g_clo[(size_t)ROWS * DMODEL];
// q/k/v split, layout [b][h][s][d]
__device__ bf g_qh[(size_t)BATCH * NHEAD * SEQ * HDIM];
__device__ bf g_ql[(size_t)BATCH * NHEAD * SEQ * HDIM];
__device__ bf g_kh[(size_t)BATCH * NHEAD * SEQ * HDIM];
__device__ bf g_kl[(size_t)BATCH * NHEAD * SEQ * HDIM];
__device__ bf g_vh[(size_t)BATCH * NHEAD * SEQ * HDIM];
__device__ bf g_vl[(size_t)BATCH * NHEAD * SEQ * HDIM];

// ---------------------------------------------------------------------------
// PTX helpers
// ---------------------------------------------------------------------------
__device__ __forceinline__ uint32_t smem_u32(const void* p) {
    uint32_t a;
    asm("{ .reg .u64 t; cvta.to.shared.u64 t, %1; cvt.u32.u64 %0, t; }" : "=r"(a) : "l"(p));
    return a;
}
#define CP16(sm, gm) asm volatile("cp.async.cg.shared.global [%0], [%1], 16;" :: "r"(sm), "l"(gm))
#define CP_COMMIT()  asm volatile("cp.async.commit_group;" ::: "memory")
#define CP_WAIT2()   asm volatile("cp.async.wait_group 2;" ::: "memory")
#define CP_WAIT1()   asm volatile("cp.async.wait_group 1;" ::: "memory")
#define CP_WAIT0()   asm volatile("cp.async.wait_group 0;" ::: "memory")

__device__ __forceinline__ void ldsm4(uint32_t* r, uint32_t addr) {
    asm volatile("ldmatrix.sync.aligned.m8n8.x4.shared.b16 {%0,%1,%2,%3}, [%4];"
                 : "=r"(r[0]), "=r"(r[1]), "=r"(r[2]), "=r"(r[3]) : "r"(addr));
}
__device__ __forceinline__ void ldsm4t(uint32_t* r, uint32_t addr) {
    asm volatile("ldmatrix.sync.aligned.m8n8.x4.trans.shared.b16 {%0,%1,%2,%3}, [%4];"
                 : "=r"(r[0]), "=r"(r[1]), "=r"(r[2]), "=r"(r[3]) : "r"(addr));
}
__device__ __forceinline__ void mma16816(float* c, const uint32_t* a, const uint32_t* b) {
    asm volatile(
        "mma.sync.aligned.m16n8k16.row.col.f32.bf16.bf16.f32 "
        "{%0,%1,%2,%3}, {%4,%5,%6,%7}, {%8,%9}, {%0,%1,%2,%3};"
        : "+f"(c[0]), "+f"(c[1]), "+f"(c[2]), "+f"(c[3])
        : "r"(a[0]), "r"(a[1]), "r"(a[2]), "r"(a[3]), "r"(b[0]), "r"(b[1]));
}
__device__ __forceinline__ float ex2(float x) {
    float y;
    asm("ex2.approx.f32 %0, %1;" : "=f"(y) : "f"(x));
    return y;
}
__device__ __forceinline__ uint32_t packbf(float x, float y) {
    __nv_bfloat162 t = __float22bfloat162_rn(make_float2(x, y));  // x -> low half
    return *(uint32_t*)&t;
}
__device__ __forceinline__ void split2(float x, float y, uint32_t& h, uint32_t& l) {
    h = packbf(x, y);
    float hx = __uint_as_float(h << 16);
    float hy = __uint_as_float(h & 0xffff0000u);
    l = packbf(x - hx, y - hy);
}

// ---------------------------------------------------------------------------
// Fused pre-pass: one launch does x-decomp + both weight transpose-decomps.
// ---------------------------------------------------------------------------
__global__ __launch_bounds__(256) void prep_kernel(
    const float* __restrict__ x, const float* __restrict__ Wq,
    const float* __restrict__ Wo,
    bf* __restrict__ xhi, bf* __restrict__ xlo,
    bf* __restrict__ wqh, bf* __restrict__ wql,
    bf* __restrict__ woh, bf* __restrict__ wol)
{
    __shared__ float t[32][33];
    const int blk = blockIdx.x, tid = threadIdx.x;

    if (blk < 4096) {
        int i = blk * 256 + tid;   // exactly covers ROWS*DMODEL/4
        float4 v = ((const float4*)x)[i];
        uint32_t h0, l0, h1, l1;
        split2(v.x, v.y, h0, l0);
        split2(v.z, v.w, h1, l1);
        *(uint2*)(xhi + 4 * (size_t)i) = make_uint2(h0, h1);
        *(uint2*)(xlo + 4 * (size_t)i) = make_uint2(l0, l1);
        return;
    }

    const float* W; bf *hi, *lo;
    int K, N, bx, by;
    if (blk < 7168) {
        int idx = blk - 4096;           // grid (96, 32)
        W = Wq; hi = wqh; lo = wql; K = DMODEL; N = QKV_N;
        bx = idx % 96; by = idx / 96;
    } else {
        int idx = blk - 7168;           // grid (32, 32)
        W = Wo; hi = woh; lo = wol; K = DMODEL; N = DMODEL;
        bx = idx & 31; by = idx >> 5;
    }
    const int tx = tid & 31, ty = tid >> 5;  // 32 x 8
    const int n0 = bx * 32, k0 = by * 32;
    #pragma unroll
    for (int i = 0; i < 4; i++)
        t[ty + i * 8][tx] = W[(size_t)(k0 + ty + i * 8) * N + n0 + tx];
    __syncthreads();
    #pragma unroll
    for (int i = 0; i < 4; i++) {
        float v = t[tx][ty + i * 8];
        bf h = __float2bfloat16(v);
        bf l = __float2bfloat16(v - __bfloat162float(h));
        size_t o = (size_t)(n0 + ty + i * 8) * K + k0 + tx;
        hi[o] = h; lo[o] = l;
    }
}

// ---------------------------------------------------------------------------
// Tensor-core GEMM via mma.sync, bf16 3-MMA split.
// R12: warp tile 32x64 (8 warps, 4x2 grid, 256 threads) -> ldsm:MMA ratio
// halves (24 ldsm / 48 MMA per warp-stage); LDSM issue floor no longer binds.
// CTA 128x128, BK=32, 4-stage cp.async ring, term-major MMA order.
// ---------------------------------------------------------------------------
#define GK 32
#define GROW 80
#define GSUB (128 * GROW)
#define GSTAGE (4 * GSUB)     // 40960
#define GNBUF 4
#define GM_DYN_BYTES (GNBUF * GSTAGE + 256)

__device__ __forceinline__ void gm_load_stage(
    uint32_t buf, const bf* gah, const bf* gal, const bf* gbh, const bf* gbl,
    int K, int tid)
{
    #pragma unroll
    for (int i = 0; i < 2; i++) {
        int c = i * 256 + tid;            // 512 16B-chunks per sub-matrix
        int row = c >> 2, col = c & 3;
        uint32_t so = (uint32_t)(row * GROW + col * 16);
        size_t g = (size_t)row * K + (size_t)col * 8;
        CP16(buf + so,            gah + g);
        CP16(buf + GSUB + so,     gal + g);
        CP16(buf + 2 * GSUB + so, gbh + g);
        CP16(buf + 3 * GSUB + so, gbl + g);
    }
}

// fr layout: [0..7]=Ah(2 tiles), [8..15]=Al, [16..31]=Bh(4 tiles), [32..47]=Bl
__device__ __forceinline__ void ld_frags(uint32_t* fr, uint32_t sb,
                                         uint32_t a_off, uint32_t b_off, uint32_t ko)
{
    ldsm4(fr + 0,  sb + a_off + ko);
    ldsm4(fr + 4,  sb + a_off + 16u * GROW + ko);
    ldsm4(fr + 8,  sb + GSUB + a_off + ko);
    ldsm4(fr + 12, sb + GSUB + a_off + 16u * GROW + ko);
    #pragma unroll
    for (int p = 0; p < 4; p++) {
        ldsm4(fr + 16 + p * 4, sb + 2u * GSUB + b_off + (uint32_t)(p * 16 * GROW) + ko);
        ldsm4(fr + 32 + p * 4, sb + 3u * GSUB + b_off + (uint32_t)(p * 16 * GROW) + ko);
    }
}

// Term-major: all Ah*Bh (16 distinct accs), then Ah*Bl, then Al*Bh.
__device__ __forceinline__ void mma_frags(float acc[2][8][4], const uint32_t* fr)
{
    const uint32_t* ah = fr;
    const uint32_t* al = fr + 8;
    const uint32_t* bh = fr + 16;
    const uint32_t* bl = fr + 32;
    #pragma unroll
    for (int i = 0; i < 2; i++)
        #pragma unroll
        for (int j = 0; j < 8; j++)
            mma16816(acc[i][j], ah + i * 4, bh + (j >> 1) * 4 + (j & 1) * 2);
    #pragma unroll
    for (int i = 0; i < 2; i++)
        #pragma unroll
        for (int j = 0; j < 8; j++)
            mma16816(acc[i][j], ah + i * 4, bl + (j >> 1) * 4 + (j & 1) * 2);
    #pragma unroll
    for (int i = 0; i < 2; i++)
        #pragma unroll
        for (int j = 0; j < 8; j++)
            mma16816(acc[i][j], al + i * 4, bh + (j >> 1) * 4 + (j & 1) * 2);
}

template<int EPI>
__global__ __launch_bounds__(256, 1) void gemm_hmma_x3(
    const bf* __restrict__ Ah, const bf* __restrict__ Al,
    const bf* __restrict__ Bh, const bf* __restrict__ Bl,
    const float* __restrict__ bias, float* __restrict__ C,
    bf* __restrict__ oqh, bf* __restrict__ oql,
    bf* __restrict__ okh, bf* __restrict__ okl,
    bf* __restrict__ ovh, bf* __restrict__ ovl,
    int M, int N, int K)
{
    extern __shared__ __align__(128) char dynsm[];
    const uint32_t smbase = smem_u32(dynsm);

    const int tid = threadIdx.x;
    const int wid = tid >> 5, lane = tid & 31;
    const int wr = wid >> 1, wc = wid & 1;          // warp grid 4 x 2
    const int m0 = blockIdx.y * 128, n0 = blockIdx.x * 128;

    const bf* ah0 = Ah + (size_t)m0 * K;
    const bf* al0 = Al + (size_t)m0 * K;
    const bf* bh0 = Bh + (size_t)n0 * K;
    const bf* bl0 = Bl + (size_t)n0 * K;

    const uint32_t a_off = (uint32_t)((wr * 32 + (lane & 15)) * GROW + (lane >> 4) * 16);
    const uint32_t b_off = (uint32_t)((wc * 64 + (lane >> 4) * 8 + (lane & 7)) * GROW
                                      + (((lane & 15) >> 3) * 16));

    float acc[2][8][4];
    #pragma unroll
    for (int i = 0; i < 2; i++)
        #pragma unroll
        for (int j = 0; j < 8; j++)
            #pragma unroll
            for (int r = 0; r < 4; r++) acc[i][j][r] = 0.f;

    const int NS = K / GK;   // 32

    gm_load_stage(smbase,              ah0,          al0,          bh0,          bl0,          K, tid);
    CP_COMMIT();
    gm_load_stage(smbase + GSTAGE,     ah0 + GK,     al0 + GK,     bh0 + GK,     bl0 + GK,     K, tid);
    CP_COMMIT();
    gm_load_stage(smbase + 2 * GSTAGE, ah0 + 2 * GK, al0 + 2 * GK, bh0 + 2 * GK, bl0 + 2 * GK, K, tid);
    CP_COMMIT();

    for (int s = 0; s < NS; s++) {
        CP_WAIT2();
        __syncthreads();

        const uint32_t sb = smbase + (uint32_t)(s & 3) * GSTAGE;
        uint32_t f0[48], f1[48];
        ld_frags(f0, sb, a_off, b_off, 0);     // kk0 fragments first

        int t = s + 3;                          // then global prefetch
        if (t < NS)
            gm_load_stage(smbase + (uint32_t)(t & 3) * GSTAGE,
                          ah0 + (size_t)t * GK, al0 + (size_t)t * GK,
                          bh0 + (size_t)t * GK, bl0 + (size_t)t * GK, K, tid);
        CP_COMMIT();

        ld_frags(f1, sb, a_off, b_off, 32);    // kk1 fragments before any mma

        mma_frags(acc, f0);
        mma_frags(acc, f1);
    }

    const int er = m0 + wr * 32 + (lane >> 2);
    const int ec = n0 + wc * 64 + 2 * (lane & 3);

    if (EPI == 0) {
        #pragma unroll
        for (int i = 0; i < 2; i++)
            #pragma unroll
            for (int j = 0; j < 8; j++) {
                int r = er + i * 16, c = ec + j * 8;
                *(float2*)(C + (size_t)r * N + c) =
                    make_float2(acc[i][j][0], acc[i][j][1]);
                *(float2*)(C + (size_t)(r + 8) * N + c) =
                    make_float2(acc[i][j][2], acc[i][j][3]);
            }
    } else {
        const int part = ec >> 10;
        bf *dh, *dl;
        if (part == 0)      { dh = oqh; dl = oql; }
        else if (part == 1) { dh = okh; dl = okl; }
        else                { dh = ovh; dl = ovl; }
        // q scale folded in LOG2 domain: 1/sqrt(64) * log2(e)
        const float sc = (part == 0) ? 0.18033688f : 1.0f;
        #pragma unroll
        for (int i = 0; i < 2; i++)
            #pragma unroll
            for (int j = 0; j < 8; j++) {
                int r = er + i * 16, c = ec + j * 8;
                int hh = (c >> 6) & 15, d = c & 63;
                float b0 = bias[c], b1 = bias[c + 1];
                uint32_t ph, pl;
                split2((acc[i][j][0] + b0) * sc, (acc[i][j][1] + b1) * sc, ph, pl);
                size_t off = (((size_t)(r >> 11) * NHEAD + hh) * SEQ + (r & 2047)) * HDIM + d;
                *(uint32_t*)(dh + off) = ph;
                *(uint32_t*)(dl + off) = pl;
                split2((acc[i][j][2] + b0) * sc, (acc[i][j][3] + b1) * sc, ph, pl);
                int r2 = r + 8;
                off = (((size_t)(r2 >> 11) * NHEAD + hh) * SEQ + (r2 & 2047)) * HDIM + d;
                *(uint32_t*)(dh + off) = ph;
                *(uint32_t*)(dl + off) = pl;
            }
    }
}

// ---------------------------------------------------------------------------
// HMMA flash attention, log2-domain softmax; MMAs term-major (unchanged R11).
// CTA = 128 q rows x one (b,h); 8 warps, warp = 16 q x 64 keys.
// ---------------------------------------------------------------------------
#define AROW 144
#define AQ_BYTES (128 * AROW)
#define AKV_BYTES (64 * AROW)
#define AST (4 * AKV_BYTES)
#define ATT_SMEM (2 * AQ_BYTES + 3 * AST)

__device__ __forceinline__ void att_load_kv(
    uint32_t base, const bf* khp, const bf* klp, const bf* vhp, const bf* vlp,
    int kt, int tid)
{
    #pragma unroll
    for (int i = 0; i < 2; i++) {
        int c = i * 256 + tid;
        int row = c >> 3, col = c & 7;
        uint32_t so = (uint32_t)(row * AROW + col * 16);
        size_t g = (size_t)(kt * 64 + row) * HDIM + col * 8;
        CP16(base + so,                   khp + g);
        CP16(base + AKV_BYTES + so,       klp + g);
        CP16(base + 2 * AKV_BYTES + so,   vhp + g);
        CP16(base + 3 * AKV_BYTES + so,   vlp + g);
    }
}

__device__ __forceinline__ void ld_kfr(uint32_t* f, uint32_t kvb, uint32_t kb_off, int ks)
{
    #pragma unroll
    for (int g = 0; g < 4; g++) {
        uint32_t ad = kvb + kb_off + (uint32_t)(g * 16 * AROW) + (uint32_t)(ks * 32);
        ldsm4(f + g * 4, ad);
        ldsm4(f + 16 + g * 4, ad + AKV_BYTES);
    }
}
__device__ __forceinline__ void ld_vfr(uint32_t* f, uint32_t kvb, uint32_t vb_off, int ks)
{
    #pragma unroll
    for (int g = 0; g < 4; g++) {
        uint32_t ad = kvb + 2 * AKV_BYTES + vb_off
                    + (uint32_t)(ks * 16 * AROW) + (uint32_t)(g * 32);
        ldsm4t(f + g * 4, ad);
        ldsm4t(f + 16 + g * 4, ad + AKV_BYTES);
    }
}

__global__ __launch_bounds__(256) void flash_hmma(
    const bf* __restrict__ qh, const bf* __restrict__ ql,
    const bf* __restrict__ kh, const bf* __restrict__ kl,
    const bf* __restrict__ vh, const bf* __restrict__ vl,
    bf* __restrict__ chi, bf* __restrict__ clo)
{
    extern __shared__ __align__(128) char asmbuf[];
    const uint32_t sb = smem_u32(asmbuf);
    const int tid = threadIdx.x, wid = tid >> 5, lane = tid & 31;
    const int qt = 15 - (int)blockIdx.x;
    const int h = blockIdx.y, b = blockIdx.z;
    const int q0 = qt * 128;
    const int ktmax = 2 * qt + 1;

    const size_t headoff = ((size_t)b * NHEAD + h) * SEQ * HDIM;
    const bf* qhp = qh + headoff + (size_t)q0 * HDIM;
    const bf* qlp = ql + headoff + (size_t)q0 * HDIM;
    const bf* khp = kh + headoff;
    const bf* klp = kl + headoff;
    const bf* vhp = vh + headoff;
    const bf* vlp = vl + headoff;

    #pragma unroll
    for (int i = 0; i < 4; i++) {
        int c = i * 256 + tid;
        int row = c >> 3, col = c & 7;
        uint32_t so = (uint32_t)(row * AROW + col * 16);
        size_t g = (size_t)row * HDIM + col * 8;
        CP16(sb + so,            qhp + g);
        CP16(sb + AQ_BYTES + so, qlp + g);
    }
    att_load_kv(sb + 2 * AQ_BYTES, khp, klp, vhp, vlp, 0, tid);
    CP_COMMIT();
    att_load_kv(sb + 2 * AQ_BYTES + AST, khp, klp, vhp, vlp, 1, tid);
    CP_COMMIT();

    float s[8][4], acc[8][4];
    float m0v = -1e30f, m1v = -1e30f, l0v = 0.f, l1v = 0.f;
    #pragma unroll
    for (int nc = 0; nc < 8; nc++) {
        acc[nc][0] = acc[nc][1] = acc[nc][2] = acc[nc][3] = 0.f;
    }
    uint32_t qfh[16], qfl[16];

    const uint32_t a_off = (uint32_t)((wid * 16 + (lane & 15)) * AROW + (lane >> 4) * 16);
    const uint32_t kb_off = (uint32_t)(((lane >> 4) * 8 + (lane & 7)) * AROW
                                       + (((lane & 15) >> 3) * 16));
    const uint32_t vb_off = (uint32_t)((lane & 15) * AROW + (lane >> 4) * 16);

    for (int kt = 0; kt <= ktmax; kt++) {
        if (kt < ktmax) { CP_WAIT1(); } else { CP_WAIT0(); }
        __syncthreads();

        if (kt == 0) {
            #pragma unroll
            for (int ks = 0; ks < 4; ks++) {
                ldsm4(&qfh[ks * 4], sb + a_off + (uint32_t)(ks * 32));
                ldsm4(&qfl[ks * 4], sb + AQ_BYTES + a_off + (uint32_t)(ks * 32));
            }
        }
        int t = kt + 2;
        if (t <= ktmax) {
            att_load_kv(sb + 2 * AQ_BYTES + (uint32_t)(t % 3) * AST,
                        khp, klp, vhp, vlp, t, tid);
            CP_COMMIT();
        }
        const uint32_t kvb = sb + 2 * AQ_BYTES + (uint32_t)(kt % 3) * AST;

        // ---- scores = Q K^T (3-MMA split), term-major issue order ----
        #pragma unroll
        for (int nc = 0; nc < 8; nc++) {
            s[nc][0] = s[nc][1] = s[nc][2] = s[nc][3] = 0.f;
        }
        {
            uint32_t kfb[2][32];
            ld_kfr(kfb[0], kvb, kb_off, 0);
            #pragma unroll
            for (int ks = 0; ks < 4; ks++) {
                if (ks < 3) ld_kfr(kfb[(ks + 1) & 1], kvb, kb_off, ks + 1);
                const uint32_t* kf = kfb[ks & 1];
                const uint32_t* kg = kf + 16;
                #pragma unroll
                for (int nc = 0; nc < 8; nc++)
                    mma16816(s[nc], &qfh[ks * 4], kf + (nc >> 1) * 4 + (nc & 1) * 2);
                #pragma unroll
                for (int nc = 0; nc < 8; nc++)
                    mma16816(s[nc], &qfl[ks * 4], kf + (nc >> 1) * 4 + (nc & 1) * 2);
                #pragma unroll
                for (int nc = 0; nc < 8; nc++)
                    mma16816(s[nc], &qfh[ks * 4], kg + (nc >> 1) * 4 + (nc & 1) * 2);
            }
        }

        // ---- online softmax (log2 domain; scores pre-scaled by log2e/8) ----
        if (kt >= 2 * qt) {
            const int keyb = kt * 64 + 2 * (lane & 3);
            const int r0 = q0 + wid * 16 + (lane >> 2);
            #pragma unroll
            for (int nc = 0; nc < 8; nc++) {
                int k0 = keyb + nc * 8;
                if (k0     > r0)     s[nc][0] = -1e30f;
                if (k0 + 1 > r0)     s[nc][1] = -1e30f;
                if (k0     > r0 + 8) s[nc][2] = -1e30f;
                if (k0 + 1 > r0 + 8) s[nc][3] = -1e30f;
            }
        }
        float mx0 = -1e30f, mx1 = -1e30f;
        #pragma unroll
        for (int nc = 0; nc < 8; nc++) {
            mx0 = fmaxf(mx0, fmaxf(s[nc][0], s[nc][1]));
            mx1 = fmaxf(mx1, fmaxf(s[nc][2], s[nc][3]));
        }
        mx0 = fmaxf(mx0, __shfl_xor_sync(0xffffffffu, mx0, 1));
        mx0 = fmaxf(mx0, __shfl_xor_sync(0xffffffffu, mx0, 2));
        mx1 = fmaxf(mx1, __shfl_xor_sync(0xffffffffu, mx1, 1));
        mx1 = fmaxf(mx1, __shfl_xor_sync(0xffffffffu, mx1, 2));
        float mn0 = fmaxf(m0v, mx0), mn1 = fmaxf(m1v, mx1);
        float c0 = ex2(m0v - mn0), c1 = ex2(m1v - mn1);
        float su0 = 0.f, su1 = 0.f;
        #pragma unroll
        for (int nc = 0; nc < 8; nc++) {
            s[nc][0] = ex2(s[nc][0] - mn0);
            s[nc][1] = ex2(s[nc][1] - mn0);
            s[nc][2] = ex2(s[nc][2] - mn1);
            s[nc][3] = ex2(s[nc][3] - mn1);
            su0 += s[nc][0] + s[nc][1];
            su1 += s[nc][2] + s[nc][3];
        }
        su0 += __shfl_xor_sync(0xffffffffu, su0, 1);
        su0 += __shfl_xor_sync(0xffffffffu, su0, 2);
        su1 += __shfl_xor_sync(0xffffffffu, su1, 1);
        su1 += __shfl_xor_sync(0xffffffffu, su1, 2);
        l0v = l0v * c0 + su0;
        l1v = l1v * c1 + su1;
        m0v = mn0; m1v = mn1;
        #pragma unroll
        for (int nc = 0; nc < 8; nc++) {
            acc[nc][0] *= c0; acc[nc][1] *= c0;
            acc[nc][2] *= c1; acc[nc][3] *= c1;
        }

        // ---- ctx += P V (3-MMA split), term-major issue order ----
        {
            uint32_t vfb[2][32];
            ld_vfr(vfb[0], kvb, vb_off, 0);
            #pragma unroll
            for (int ks = 0; ks < 4; ks++) {
                if (ks < 3) ld_vfr(vfb[(ks + 1) & 1], kvb, vb_off, ks + 1);
                uint32_t ph[4], pl[4];
                split2(s[2 * ks][0],     s[2 * ks][1],     ph[0], pl[0]);
                split2(s[2 * ks][2],     s[2 * ks][3],     ph[1], pl[1]);
                split2(s[2 * ks + 1][0], s[2 * ks + 1][1], ph[2], pl[2]);
                split2(s[2 * ks + 1][2], s[2 * ks + 1][3], ph[3], pl[3]);
                const uint32_t* vf = vfb[ks & 1];
                const uint32_t* vg = vf + 16;
                #pragma unroll
                for (int nc = 0; nc < 8; nc++)
                    mma16816(acc[nc], ph, vf + (nc >> 1) * 4 + (nc & 1) * 2);
                #pragma unroll
                for (int nc = 0; nc < 8; nc++)
                    mma16816(acc[nc], pl, vf + (nc >> 1) * 4 + (nc & 1) * 2);
                #pragma unroll
                for (int nc = 0; nc < 8; nc++)
                    mma16816(acc[nc], ph, vg + (nc >> 1) * 4 + (nc & 1) * 2);
            }
        }
    }

    float i0 = 1.f / l0v, i1 = 1.f / l1v;
    const int r0 = q0 + wid * 16 + (lane >> 2);
    const int cb = h * HDIM + 2 * (lane & 3);
    #pragma unroll
    for (int nc = 0; nc < 8; nc++) {
        int cc = cb + nc * 8;
        uint32_t ph, pl;
        split2(acc[nc][0] * i0, acc[nc][1] * i0, ph, pl);
        size_t off = (size_t)(b * SEQ + r0) * DMODEL + cc;
        *(uint32_t*)(chi + off) = ph;
        *(uint32_t*)(clo + off) = pl;
        split2(acc[nc][2] * i1, acc[nc][3] * i1, ph, pl);
        off = (size_t)(b * SEQ + r0 + 8) * DMODEL + cc;
        *(uint32_t*)(chi + off) = ph;
        *(uint32_t*)(clo + off) = pl;
    }
}

// ---------------------------------------------------------------------------
extern "C" void kernel_launch(void* const* d_in, const int* in_sizes, int n_in,
                              void* d_out, int out_size)
{
    (void)in_sizes; (void)n_in; (void)out_size;
    const float* x     = (const float*)d_in[0];
    const float* W_qkv = (const float*)d_in[1];
    const float* b_qkv = (const float*)d_in[2];
    const float* W_out = (const float*)d_in[3];
    float* out = (float*)d_out;

    bf *xhi, *xlo, *wqh, *wql, *woh, *wol, *chi, *clo;
    bf *qh, *ql, *kh, *kl, *vh, *vl;
    cudaGetSymbolAddress((void**)&xhi, g_xhi);
    cudaGetSymbolAddress((void**)&xlo, g_xlo);
    cudaGetSymbolAddress((void**)&wqh, g_wqh);
    cudaGetSymbolAddress((void**)&wql, g_wql);
    cudaGetSymbolAddress((void**)&woh, g_woh);
    cudaGetSymbolAddress((void**)&wol, g_wol);
    cudaGetSymbolAddress((void**)&chi, g_chi);
    cudaGetSymbolAddress((void**)&clo, g_clo);
    cudaGetSymbolAddress((void**)&qh, g_qh);
    cudaGetSymbolAddress((void**)&ql, g_ql);
    cudaGetSymbolAddress((void**)&kh, g_kh);
    cudaGetSymbolAddress((void**)&kl, g_kl);
    cudaGetSymbolAddress((void**)&vh, g_vh);
    cudaGetSymbolAddress((void**)&vl, g_vl);

    cudaFuncSetAttribute(gemm_hmma_x3<0>, cudaFuncAttributeMaxDynamicSharedMemorySize,
                         GM_DYN_BYTES);
    cudaFuncSetAttribute(gemm_hmma_x3<1>, cudaFuncAttributeMaxDynamicSharedMemorySize,
                         GM_DYN_BYTES);
    cudaFuncSetAttribute(flash_hmma, cudaFuncAttributeMaxDynamicSharedMemorySize,
                         ATT_SMEM);

    // fused pre-pass (one launch)
    prep_kernel<<<8192, 256>>>(x, W_qkv, W_out, xhi, xlo, wqh, wql, woh, wol);

    gemm_hmma_x3<1><<<dim3(QKV_N / 128, ROWS / 128), 256, GM_DYN_BYTES>>>(
        xhi, xlo, wqh, wql, b_qkv, nullptr,
        qh, ql, kh, kl, vh, vl, ROWS, QKV_N, DMODEL);

    flash_hmma<<<dim3(16, NHEAD, BATCH), 256, ATT_SMEM>>>(
        qh, ql, kh, kl, vh, vl, chi, clo);

    gemm_hmma_x3<0><<<dim3(DMODEL / 128, ROWS / 128), 256, GM_DYN_BYTES>>>(
        chi, clo, woh, wol, nullptr, out,
        nullptr, nullptr, nullptr, nullptr, nullptr, nullptr,
        ROWS, DMODEL, DMODEL);
}

// round 13
// speedup vs baseline: 1.0155x; 1.0155x over previous
#include <cuda_runtime.h>
#include <cuda_bf16.h>
#include <math.h>
#include <stdint.h>

#define BATCH 2
#define SEQ   2048
#define DMODEL 1024
#define NHEAD 16
#define HDIM  64
#define ROWS  (BATCH*SEQ)          // 4096
#define QKV_N (3*DMODEL)           // 3072

typedef __nv_bfloat16 bf;

// ---------------------------------------------------------------------------
// Device scratch
// ---------------------------------------------------------------------------
__device__ bf g_xhi[(size_t)ROWS * DMODEL];
__device__ bf g_xlo[(size_t)ROWS * DMODEL];
__device__ bf g_wqh[(size_t)QKV_N * DMODEL];   // W_qkv^T [3072][1024]
__device__ bf g_wql[(size_t)QKV_N * DMODEL];
__device__ bf g_woh[(size_t)DMODEL * DMODEL];  // W_out^T [1024][1024]
__device__ bf g_wol[(size_t)DMODEL * DMODEL];
__device__ bf g_chi[(size_t)ROWS * DMODEL];    // ctx hi/lo [row][1024]
__device__ bf g_clo[(size_t)ROWS * DMODEL];
// q/k/v split, layout [b][h][s][d]
__device__ bf g_qh[(size_t)BATCH * NHEAD * SEQ * HDIM];
__device__ bf g_ql[(size_t)BATCH * NHEAD * SEQ * HDIM];
__device__ bf g_kh[(size_t)BATCH * NHEAD * SEQ * HDIM];
__device__ bf g_kl[(size_t)BATCH * NHEAD * SEQ * HDIM];
__device__ bf g_vh[(size_t)BATCH * NHEAD * SEQ * HDIM];
__device__ bf g_vl[(size_t)BATCH * NHEAD * SEQ * HDIM];

// ---------------------------------------------------------------------------
// PTX helpers
// ---------------------------------------------------------------------------
__device__ __forceinline__ uint32_t smem_u32(const void* p) {
    uint32_t a;
    asm("{ .reg .u64 t; cvta.to.shared.u64 t, %1; cvt.u32.u64 %0, t; }" : "=r"(a) : "l"(p));
    return a;
}
#define CP16(sm, gm) asm volatile("cp.async.cg.shared.global [%0], [%1], 16;" :: "r"(sm), "l"(gm))
#define CP_COMMIT()  asm volatile("cp.async.commit_group;" ::: "memory")
#define CP_WAIT1()   asm volatile("cp.async.wait_group 1;" ::: "memory")
#define CP_WAIT0()   asm volatile("cp.async.wait_group 0;" ::: "memory")

__device__ __forceinline__ void ldsm4(uint32_t* r, uint32_t addr) {
    asm volatile("ldmatrix.sync.aligned.m8n8.x4.shared.b16 {%0,%1,%2,%3}, [%4];"
                 : "=r"(r[0]), "=r"(r[1]), "=r"(r[2]), "=r"(r[3]) : "r"(addr));
}
__device__ __forceinline__ void ldsm4t(uint32_t* r, uint32_t addr) {
    asm volatile("ldmatrix.sync.aligned.m8n8.x4.trans.shared.b16 {%0,%1,%2,%3}, [%4];"
                 : "=r"(r[0]), "=r"(r[1]), "=r"(r[2]), "=r"(r[3]) : "r"(addr));
}
__device__ __forceinline__ void mma16816(float* c, const uint32_t* a, const uint32_t* b) {
    asm volatile(
        "mma.sync.aligned.m16n8k16.row.col.f32.bf16.bf16.f32 "
        "{%0,%1,%2,%3}, {%4,%5,%6,%7}, {%8,%9}, {%0,%1,%2,%3};"
        : "+f"(c[0]), "+f"(c[1]), "+f"(c[2]), "+f"(c[3])
        : "r"(a[0]), "r"(a[1]), "r"(a[2]), "r"(a[3]), "r"(b[0]), "r"(b[1]));
}
__device__ __forceinline__ float ex2(float x) {
    float y;
    asm("ex2.approx.f32 %0, %1;" : "=f"(y) : "f"(x));
    return y;
}
__device__ __forceinline__ uint32_t packbf(float x, float y) {
    __nv_bfloat162 t = __float22bfloat162_rn(make_float2(x, y));  // x -> low half
    return *(uint32_t*)&t;
}
__device__ __forceinline__ void split2(float x, float y, uint32_t& h, uint32_t& l) {
    h = packbf(x, y);
    float hx = __uint_as_float(h << 16);
    float hy = __uint_as_float(h & 0xffff0000u);
    l = packbf(x - hx, y - hy);
}

// ---------------------------------------------------------------------------
// Fused pre-pass (R10/R11 proven)
// ---------------------------------------------------------------------------
__global__ __launch_bounds__(256) void prep_kernel(
    const float* __restrict__ x, const float* __restrict__ Wq,
    const float* __restrict__ Wo,
    bf* __restrict__ xhi, bf* __restrict__ xlo,
    bf* __restrict__ wqh, bf* __restrict__ wql,
    bf* __restrict__ woh, bf* __restrict__ wol)
{
    __shared__ float t[32][33];
    const int blk = blockIdx.x, tid = threadIdx.x;

    if (blk < 4096) {
        int i = blk * 256 + tid;
        float4 v = ((const float4*)x)[i];
        uint32_t h0, l0, h1, l1;
        split2(v.x, v.y, h0, l0);
        split2(v.z, v.w, h1, l1);
        *(uint2*)(xhi + 4 * (size_t)i) = make_uint2(h0, h1);
        *(uint2*)(xlo + 4 * (size_t)i) = make_uint2(l0, l1);
        return;
    }

    const float* W; bf *hi, *lo;
    int K, N, bx, by;
    if (blk < 7168) {
        int idx = blk - 4096;
        W = Wq; hi = wqh; lo = wql; K = DMODEL; N = QKV_N;
        bx = idx % 96; by = idx / 96;
    } else {
        int idx = blk - 7168;
        W = Wo; hi = woh; lo = wol; K = DMODEL; N = DMODEL;
        bx = idx & 31; by = idx >> 5;
    }
    const int tx = tid & 31, ty = tid >> 5;
    const int n0 = bx * 32, k0 = by * 32;
    #pragma unroll
    for (int i = 0; i < 4; i++)
        t[ty + i * 8][tx] = W[(size_t)(k0 + ty + i * 8) * N + n0 + tx];
    __syncthreads();
    #pragma unroll
    for (int i = 0; i < 4; i++) {
        float v = t[tx][ty + i * 8];
        bf h = __float2bfloat16(v);
        bf l = __float2bfloat16(v - __bfloat162float(h));
        size_t o = (size_t)(n0 + ty + i * 8) * K + k0 + tx;
        hi[o] = h; lo[o] = l;
    }
}

// ---------------------------------------------------------------------------
// Tensor-core GEMM, bf16 3-MMA split.
// R13: CTA 256x128, 16 warps (4x4), warp tile 64x32 -> 24 ldsm / 96 MMA
// per warp-stage (HMMA-bound, 2x slack over LDSM floor). Term-sequential
// fragment reuse keeps regs ~115. BK=32, 3-stage cp.async ring, wait1.
// ---------------------------------------------------------------------------
#define GK 32
#define GROW 80
#define GSUBA (256 * GROW)    // 20480 (A hi or lo)
#define GSUBB (128 * GROW)    // 10240 (B hi or lo)
#define GOFF_AL GSUBA
#define GOFF_BH (2 * GSUBA)
#define GOFF_BL (2 * GSUBA + GSUBB)
#define GSTAGE (2 * GSUBA + 2 * GSUBB)   // 61440
#define GNBUF 3
#define GM_DYN_BYTES (GNBUF * GSTAGE + 256)   // 184576

__device__ __forceinline__ void gm_load_stage(
    uint32_t buf, const bf* gah, const bf* gal, const bf* gbh, const bf* gbl,
    int K, int tid)
{
    // A: 256 rows x 4 chunks = 1024 chunks -> 2 rounds of 512 threads
    #pragma unroll
    for (int i = 0; i < 2; i++) {
        int c = i * 512 + tid;
        int row = c >> 2, col = c & 3;
        uint32_t so = (uint32_t)(row * GROW + col * 16);
        size_t g = (size_t)row * K + (size_t)col * 8;
        CP16(buf + so,           gah + g);
        CP16(buf + GOFF_AL + so, gal + g);
    }
    // B: 128 rows x 4 chunks = 512 chunks -> 1 round
    {
        int row = tid >> 2, col = tid & 3;
        uint32_t so = (uint32_t)(row * GROW + col * 16);
        size_t g = (size_t)row * K + (size_t)col * 8;
        CP16(buf + GOFF_BH + so, gbh + g);
        CP16(buf + GOFF_BL + so, gbl + g);
    }
}

template<int EPI>
__global__ __launch_bounds__(512, 1) void gemm_hmma_x3(
    const bf* __restrict__ Ah, const bf* __restrict__ Al,
    const bf* __restrict__ Bh, const bf* __restrict__ Bl,
    const float* __restrict__ bias, float* __restrict__ C,
    bf* __restrict__ oqh, bf* __restrict__ oql,
    bf* __restrict__ okh, bf* __restrict__ okl,
    bf* __restrict__ ovh, bf* __restrict__ ovl,
    int M, int N, int K)
{
    extern __shared__ __align__(128) char dynsm[];
    const uint32_t smbase = smem_u32(dynsm);

    const int tid = threadIdx.x;
    const int wid = tid >> 5, lane = tid & 31;
    const int wr = wid >> 2, wc = wid & 3;          // warp grid 4 x 4
    const int m0 = blockIdx.y * 256, n0 = blockIdx.x * 128;

    const bf* ah0 = Ah + (size_t)m0 * K;
    const bf* al0 = Al + (size_t)m0 * K;
    const bf* bh0 = Bh + (size_t)n0 * K;
    const bf* bl0 = Bl + (size_t)n0 * K;

    // warp tile 64x32: A rows wr*64..+63 (4 tiles), B rows wc*32..+31 (2 pairs)
    const uint32_t a_off = (uint32_t)((wr * 64 + (lane & 15)) * GROW + (lane >> 4) * 16);
    const uint32_t b_off = (uint32_t)((wc * 32 + (lane >> 4) * 8 + (lane & 7)) * GROW
                                      + (((lane & 15) >> 3) * 16));

    float acc[4][4][4];
    #pragma unroll
    for (int i = 0; i < 4; i++)
        #pragma unroll
        for (int j = 0; j < 4; j++)
            #pragma unroll
            for (int r = 0; r < 4; r++) acc[i][j][r] = 0.f;

    const int NS = K / GK;   // 32

    gm_load_stage(smbase,          ah0,      al0,      bh0,      bl0,      K, tid);
    CP_COMMIT();
    gm_load_stage(smbase + GSTAGE, ah0 + GK, al0 + GK, bh0 + GK, bl0 + GK, K, tid);
    CP_COMMIT();

    for (int s = 0; s < NS; s++) {
        CP_WAIT1();
        __syncthreads();

        const uint32_t sb = smbase + (uint32_t)(s % 3) * GSTAGE;

        #pragma unroll
        for (int kk = 0; kk < 2; kk++) {
            const uint32_t ko = (uint32_t)(kk * 32);
            uint32_t fa[16], fb[8], fb2[8];
            // Ah + Bh
            #pragma unroll
            for (int i = 0; i < 4; i++)
                ldsm4(fa + i * 4, sb + a_off + (uint32_t)(i * 16 * GROW) + ko);
            #pragma unroll
            for (int p = 0; p < 2; p++)
                ldsm4(fb + p * 4, sb + GOFF_BH + b_off + (uint32_t)(p * 16 * GROW) + ko);

            if (kk == 0) {   // global prefetch early, once per stage
                int t = s + 2;
                if (t < NS)
                    gm_load_stage(smbase + (uint32_t)(t % 3) * GSTAGE,
                                  ah0 + (size_t)t * GK, al0 + (size_t)t * GK,
                                  bh0 + (size_t)t * GK, bl0 + (size_t)t * GK, K, tid);
                CP_COMMIT();
            }

            // Ah * Bh
            #pragma unroll
            for (int i = 0; i < 4; i++)
                #pragma unroll
                for (int j = 0; j < 4; j++)
                    mma16816(acc[i][j], fa + i * 4, fb + (j >> 1) * 4 + (j & 1) * 2);
            // Bl, then Ah * Bl
            #pragma unroll
            for (int p = 0; p < 2; p++)
                ldsm4(fb2 + p * 4, sb + GOFF_BL + b_off + (uint32_t)(p * 16 * GROW) + ko);
            #pragma unroll
            for (int i = 0; i < 4; i++)
                #pragma unroll
                for (int j = 0; j < 4; j++)
                    mma16816(acc[i][j], fa + i * 4, fb2 + (j >> 1) * 4 + (j & 1) * 2);
            // Al (reuse fa), then Al * Bh
            #pragma unroll
            for (int i = 0; i < 4; i++)
                ldsm4(fa + i * 4, sb + GOFF_AL + a_off + (uint32_t)(i * 16 * GROW) + ko);
            #pragma unroll
            for (int i = 0; i < 4; i++)
                #pragma unroll
                for (int j = 0; j < 4; j++)
                    mma16816(acc[i][j], fa + i * 4, fb + (j >> 1) * 4 + (j & 1) * 2);
        }
    }

    const int er = m0 + wr * 64 + (lane >> 2);
    const int ec = n0 + wc * 32 + 2 * (lane & 3);

    if (EPI == 0) {
        #pragma unroll
        for (int i = 0; i < 4; i++)
            #pragma unroll
            for (int j = 0; j < 4; j++) {
                int r = er + i * 16, c = ec + j * 8;
                *(float2*)(C + (size_t)r * N + c) =
                    make_float2(acc[i][j][0], acc[i][j][1]);
                *(float2*)(C + (size_t)(r + 8) * N + c) =
                    make_float2(acc[i][j][2], acc[i][j][3]);
            }
    } else {
        const int part = ec >> 10;
        bf *dh, *dl;
        if (part == 0)      { dh = oqh; dl = oql; }
        else if (part == 1) { dh = okh; dl = okl; }
        else                { dh = ovh; dl = ovl; }
        // q scale folded in LOG2 domain: 1/sqrt(64) * log2(e)
        const float sc = (part == 0) ? 0.18033688f : 1.0f;
        #pragma unroll
        for (int i = 0; i < 4; i++)
            #pragma unroll
            for (int j = 0; j < 4; j++) {
                int r = er + i * 16, c = ec + j * 8;
                int hh = (c >> 6) & 15, d = c & 63;
                float b0 = bias[c], b1 = bias[c + 1];
                uint32_t ph, pl;
                split2((acc[i][j][0] + b0) * sc, (acc[i][j][1] + b1) * sc, ph, pl);
                size_t off = (((size_t)(r >> 11) * NHEAD + hh) * SEQ + (r & 2047)) * HDIM + d;
                *(uint32_t*)(dh + off) = ph;
                *(uint32_t*)(dl + off) = pl;
                split2((acc[i][j][2] + b0) * sc, (acc[i][j][3] + b1) * sc, ph, pl);
                int r2 = r + 8;
                off = (((size_t)(r2 >> 11) * NHEAD + hh) * SEQ + (r2 & 2047)) * HDIM + d;
                *(uint32_t*)(dh + off) = ph;
                *(uint32_t*)(dl + off) = pl;
            }
    }
}

// ---------------------------------------------------------------------------
// HMMA flash attention (R11 proven, unchanged).
// ---------------------------------------------------------------------------
#define AROW 144
#define AQ_BYTES (128 * AROW)
#define AKV_BYTES (64 * AROW)
#define AST (4 * AKV_BYTES)
#define ATT_SMEM (2 * AQ_BYTES + 3 * AST)

__device__ __forceinline__ void att_load_kv(
    uint32_t base, const bf* khp, const bf* klp, const bf* vhp, const bf* vlp,
    int kt, int tid)
{
    #pragma unroll
    for (int i = 0; i < 2; i++) {
        int c = i * 256 + tid;
        int row = c >> 3, col = c & 7;
        uint32_t so = (uint32_t)(row * AROW + col * 16);
        size_t g = (size_t)(kt * 64 + row) * HDIM + col * 8;
        CP16(base + so,                   khp + g);
        CP16(base + AKV_BYTES + so,       klp + g);
        CP16(base + 2 * AKV_BYTES + so,   vhp + g);
        CP16(base + 3 * AKV_BYTES + so,   vlp + g);
    }
}

__device__ __forceinline__ void ld_kfr(uint32_t* f, uint32_t kvb, uint32_t kb_off, int ks)
{
    #pragma unroll
    for (int g = 0; g < 4; g++) {
        uint32_t ad = kvb + kb_off + (uint32_t)(g * 16 * AROW) + (uint32_t)(ks * 32);
        ldsm4(f + g * 4, ad);
        ldsm4(f + 16 + g * 4, ad + AKV_BYTES);
    }
}
__device__ __forceinline__ void ld_vfr(uint32_t* f, uint32_t kvb, uint32_t vb_off, int ks)
{
    #pragma unroll
    for (int g = 0; g < 4; g++) {
        uint32_t ad = kvb + 2 * AKV_BYTES + vb_off
                    + (uint32_t)(ks * 16 * AROW) + (uint32_t)(g * 32);
        ldsm4t(f + g * 4, ad);
        ldsm4t(f + 16 + g * 4, ad + AKV_BYTES);
    }
}

__global__ __launch_bounds__(256) void flash_hmma(
    const bf* __restrict__ qh, const bf* __restrict__ ql,
    const bf* __restrict__ kh, const bf* __restrict__ kl,
    const bf* __restrict__ vh, const bf* __restrict__ vl,
    bf* __restrict__ chi, bf* __restrict__ clo)
{
    extern __shared__ __align__(128) char asmbuf[];
    const uint32_t sb = smem_u32(asmbuf);
    const int tid = threadIdx.x, wid = tid >> 5, lane = tid & 31;
    const int qt = 15 - (int)blockIdx.x;
    const int h = blockIdx.y, b = blockIdx.z;
    const int q0 = qt * 128;
    const int ktmax = 2 * qt + 1;

    const size_t headoff = ((size_t)b * NHEAD + h) * SEQ * HDIM;
    const bf* qhp = qh + headoff + (size_t)q0 * HDIM;
    const bf* qlp = ql + headoff + (size_t)q0 * HDIM;
    const bf* khp = kh + headoff;
    const bf* klp = kl + headoff;
    const bf* vhp = vh + headoff;
    const bf* vlp = vl + headoff;

    #pragma unroll
    for (int i = 0; i < 4; i++) {
        int c = i * 256 + tid;
        int row = c >> 3, col = c & 7;
        uint32_t so = (uint32_t)(row * AROW + col * 16);
        size_t g = (size_t)row * HDIM + col * 8;
        CP16(sb + so,            qhp + g);
        CP16(sb + AQ_BYTES + so, qlp + g);
    }
    att_load_kv(sb + 2 * AQ_BYTES, khp, klp, vhp, vlp, 0, tid);
    CP_COMMIT();
    att_load_kv(sb + 2 * AQ_BYTES + AST, khp, klp, vhp, vlp, 1, tid);
    CP_COMMIT();

    float s[8][4], acc[8][4];
    float m0v = -1e30f, m1v = -1e30f, l0v = 0.f, l1v = 0.f;
    #pragma unroll
    for (int nc = 0; nc < 8; nc++) {
        acc[nc][0] = acc[nc][1] = acc[nc][2] = acc[nc][3] = 0.f;
    }
    uint32_t qfh[16], qfl[16];

    const uint32_t a_off = (uint32_t)((wid * 16 + (lane & 15)) * AROW + (lane >> 4) * 16);
    const uint32_t kb_off = (uint32_t)(((lane >> 4) * 8 + (lane & 7)) * AROW
                                       + (((lane & 15) >> 3) * 16));
    const uint32_t vb_off = (uint32_t)((lane & 15) * AROW + (lane >> 4) * 16);

    for (int kt = 0; kt <= ktmax; kt++) {
        if (kt < ktmax) { CP_WAIT1(); } else { CP_WAIT0(); }
        __syncthreads();

        if (kt == 0) {
            #pragma unroll
            for (int ks = 0; ks < 4; ks++) {
                ldsm4(&qfh[ks * 4], sb + a_off + (uint32_t)(ks * 32));
                ldsm4(&qfl[ks * 4], sb + AQ_BYTES + a_off + (uint32_t)(ks * 32));
            }
        }
        int t = kt + 2;
        if (t <= ktmax) {
            att_load_kv(sb + 2 * AQ_BYTES + (uint32_t)(t % 3) * AST,
                        khp, klp, vhp, vlp, t, tid);
            CP_COMMIT();
        }
        const uint32_t kvb = sb + 2 * AQ_BYTES + (uint32_t)(kt % 3) * AST;

        // ---- scores = Q K^T (3-MMA split), term-major issue order ----
        #pragma unroll
        for (int nc = 0; nc < 8; nc++) {
            s[nc][0] = s[nc][1] = s[nc][2] = s[nc][3] = 0.f;
        }
        {
            uint32_t kfb[2][32];
            ld_kfr(kfb[0], kvb, kb_off, 0);
            #pragma unroll
            for (int ks = 0; ks < 4; ks++) {
                if (ks < 3) ld_kfr(kfb[(ks + 1) & 1], kvb, kb_off, ks + 1);
                const uint32_t* kf = kfb[ks & 1];
                const uint32_t* kg = kf + 16;
                #pragma unroll
                for (int nc = 0; nc < 8; nc++)
                    mma16816(s[nc], &qfh[ks * 4], kf + (nc >> 1) * 4 + (nc & 1) * 2);
                #pragma unroll
                for (int nc = 0; nc < 8; nc++)
                    mma16816(s[nc], &qfl[ks * 4], kf + (nc >> 1) * 4 + (nc & 1) * 2);
                #pragma unroll
                for (int nc = 0; nc < 8; nc++)
                    mma16816(s[nc], &qfh[ks * 4], kg + (nc >> 1) * 4 + (nc & 1) * 2);
            }
        }

        // ---- online softmax (log2 domain; scores pre-scaled by log2e/8) ----
        if (kt >= 2 * qt) {
            const int keyb = kt * 64 + 2 * (lane & 3);
            const int r0 = q0 + wid * 16 + (lane >> 2);
            #pragma unroll
            for (int nc = 0; nc < 8; nc++) {
                int k0 = keyb + nc * 8;
                if (k0     > r0)     s[nc][0] = -1e30f;
                if (k0 + 1 > r0)     s[nc][1] = -1e30f;
                if (k0     > r0 + 8) s[nc][2] = -1e30f;
                if (k0 + 1 > r0 + 8) s[nc][3] = -1e30f;
            }
        }
        float mx0 = -1e30f, mx1 = -1e30f;
        #pragma unroll
        for (int nc = 0; nc < 8; nc++) {
            mx0 = fmaxf(mx0, fmaxf(s[nc][0], s[nc][1]));
            mx1 = fmaxf(mx1, fmaxf(s[nc][2], s[nc][3]));
        }
        mx0 = fmaxf(mx0, __shfl_xor_sync(0xffffffffu, mx0, 1));
        mx0 = fmaxf(mx0, __shfl_xor_sync(0xffffffffu, mx0, 2));
        mx1 = fmaxf(mx1, __shfl_xor_sync(0xffffffffu, mx1, 1));
        mx1 = fmaxf(mx1, __shfl_xor_sync(0xffffffffu, mx1, 2));
        float mn0 = fmaxf(m0v, mx0), mn1 = fmaxf(m1v, mx1);
        float c0 = ex2(m0v - mn0), c1 = ex2(m1v - mn1);
        float su0 = 0.f, su1 = 0.f;
        #pragma unroll
        for (int nc = 0; nc < 8; nc++) {
            s[nc][0] = ex2(s[nc][0] - mn0);
            s[nc][1] = ex2(s[nc][1] - mn0);
            s[nc][2] = ex2(s[nc][2] - mn1);
            s[nc][3] = ex2(s[nc][3] - mn1);
            su0 += s[nc][0] + s[nc][1];
            su1 += s[nc][2] + s[nc][3];
        }
        su0 += __shfl_xor_sync(0xffffffffu, su0, 1);
        su0 += __shfl_xor_sync(0xffffffffu, su0, 2);
        su1 += __shfl_xor_sync(0xffffffffu, su1, 1);
        su1 += __shfl_xor_sync(0xffffffffu, su1, 2);
        l0v = l0v * c0 + su0;
        l1v = l1v * c1 + su1;
        m0v = mn0; m1v = mn1;
        #pragma unroll
        for (int nc = 0; nc < 8; nc++) {
            acc[nc][0] *= c0; acc[nc][1] *= c0;
            acc[nc][2] *= c1; acc[nc][3] *= c1;
        }

        // ---- ctx += P V (3-MMA split), term-major issue order ----
        {
            uint32_t vfb[2][32];
            ld_vfr(vfb[0], kvb, vb_off, 0);
            #pragma unroll
            for (int ks = 0; ks < 4; ks++) {
                if (ks < 3) ld_vfr(vfb[(ks + 1) & 1], kvb, vb_off, ks + 1);
                uint32_t ph[4], pl[4];
                split2(s[2 * ks][0],     s[2 * ks][1],     ph[0], pl[0]);
                split2(s[2 * ks][2],     s[2 * ks][3],     ph[1], pl[1]);
                split2(s[2 * ks + 1][0], s[2 * ks + 1][1], ph[2], pl[2]);
                split2(s[2 * ks + 1][2], s[2 * ks + 1][3], ph[3], pl[3]);
                const uint32_t* vf = vfb[ks & 1];
                const uint32_t* vg = vf + 16;
                #pragma unroll
                for (int nc = 0; nc < 8; nc++)
                    mma16816(acc[nc], ph, vf + (nc >> 1) * 4 + (nc & 1) * 2);
                #pragma unroll
                for (int nc = 0; nc < 8; nc++)
                    mma16816(acc[nc], pl, vf + (nc >> 1) * 4 + (nc & 1) * 2);
                #pragma unroll
                for (int nc = 0; nc < 8; nc++)
                    mma16816(acc[nc], ph, vg + (nc >> 1) * 4 + (nc & 1) * 2);
            }
        }
    }

    float i0 = 1.f / l0v, i1 = 1.f / l1v;
    const int r0 = q0 + wid * 16 + (lane >> 2);
    const int cb = h * HDIM + 2 * (lane & 3);
    #pragma unroll
    for (int nc = 0; nc < 8; nc++) {
        int cc = cb + nc * 8;
        uint32_t ph, pl;
        split2(acc[nc][0] * i0, acc[nc][1] * i0, ph, pl);
        size_t off = (size_t)(b * SEQ + r0) * DMODEL + cc;
        *(uint32_t*)(chi + off) = ph;
        *(uint32_t*)(clo + off) = pl;
        split2(acc[nc][2] * i1, acc[nc][3] * i1, ph, pl);
        off = (size_t)(b * SEQ + r0 + 8) * DMODEL + cc;
        *(uint32_t*)(chi + off) = ph;
        *(uint32_t*)(clo + off) = pl;
    }
}

// ---------------------------------------------------------------------------
extern "C" void kernel_launch(void* const* d_in, const int* in_sizes, int n_in,
                              void* d_out, int out_size)
{
    (void)in_sizes; (void)n_in; (void)out_size;
    const float* x     = (const float*)d_in[0];
    const float* W_qkv = (const float*)d_in[1];
    const float* b_qkv = (const float*)d_in[2];
    const float* W_out = (const float*)d_in[3];
    float* out = (float*)d_out;

    bf *xhi, *xlo, *wqh, *wql, *woh, *wol, *chi, *clo;
    bf *qh, *ql, *kh, *kl, *vh, *vl;
    cudaGetSymbolAddress((void**)&xhi, g_xhi);
    cudaGetSymbolAddress((void**)&xlo, g_xlo);
    cudaGetSymbolAddress((void**)&wqh, g_wqh);
    cudaGetSymbolAddress((void**)&wql, g_wql);
    cudaGetSymbolAddress((void**)&woh, g_woh);
    cudaGetSymbolAddress((void**)&wol, g_wol);
    cudaGetSymbolAddress((void**)&chi, g_chi);
    cudaGetSymbolAddress((void**)&clo, g_clo);
    cudaGetSymbolAddress((void**)&qh, g_qh);
    cudaGetSymbolAddress((void**)&ql, g_ql);
    cudaGetSymbolAddress((void**)&kh, g_kh);
    cudaGetSymbolAddress((void**)&kl, g_kl);
    cudaGetSymbolAddress((void**)&vh, g_vh);
    cudaGetSymbolAddress((void**)&vl, g_vl);

    cudaFuncSetAttribute(gemm_hmma_x3<0>, cudaFuncAttributeMaxDynamicSharedMemorySize,
                         GM_DYN_BYTES);
    cudaFuncSetAttribute(gemm_hmma_x3<1>, cudaFuncAttributeMaxDynamicSharedMemorySize,
                         GM_DYN_BYTES);
    cudaFuncSetAttribute(flash_hmma, cudaFuncAttributeMaxDynamicSharedMemorySize,
                         ATT_SMEM);

    // fused pre-pass (one launch)
    prep_kernel<<<8192, 256>>>(x, W_qkv, W_out, xhi, xlo, wqh, wql, woh, wol);

    gemm_hmma_x3<1><<<dim3(QKV_N / 128, ROWS / 256), 512, GM_DYN_BYTES>>>(
        xhi, xlo, wqh, wql, b_qkv, nullptr,
        qh, ql, kh, kl, vh, vl, ROWS, QKV_N, DMODEL);

    flash_hmma<<<dim3(16, NHEAD, BATCH), 256, ATT_SMEM>>>(
        qh, ql, kh, kl, vh, vl, chi, clo);

    gemm_hmma_x3<0><<<dim3(DMODEL / 128, ROWS / 256), 512, GM_DYN_BYTES>>>(
        chi, clo, woh, wol, nullptr, out,
        nullptr, nullptr, nullptr, nullptr, nullptr, nullptr,
        ROWS, DMODEL, DMODEL);
}

// round 14
// speedup vs baseline: 1.2988x; 1.2790x over previous
#include <cuda_runtime.h>
#include <cuda_fp16.h>
#include <math.h>
#include <stdint.h>

#define BATCH 2
#define SEQ   2048
#define DMODEL 1024
#define NHEAD 16
#define HDIM  64
#define ROWS  (BATCH*SEQ)          // 4096
#define QKV_N (3*DMODEL)           // 3072

typedef __half hf;

// ---------------------------------------------------------------------------
// Device scratch (fp16)
// ---------------------------------------------------------------------------
__device__ hf g_xhi[(size_t)ROWS * DMODEL];
__device__ hf g_xlo[(size_t)ROWS * DMODEL];
__device__ hf g_wqh[(size_t)QKV_N * DMODEL];   // W_qkv^T hi [3072][1024]
__device__ hf g_wql[(size_t)QKV_N * DMODEL];   // W_qkv^T lo
__device__ hf g_woh[(size_t)DMODEL * DMODEL];  // W_out^T single fp16
__device__ hf g_chi[(size_t)ROWS * DMODEL];    // ctx hi/lo
__device__ hf g_clo[(size_t)ROWS * DMODEL];
// q split; k, v single fp16. layout [b][h][s][d]
__device__ hf g_qh[(size_t)BATCH * NHEAD * SEQ * HDIM];
__device__ hf g_ql[(size_t)BATCH * NHEAD * SEQ * HDIM];
__device__ hf g_kh[(size_t)BATCH * NHEAD * SEQ * HDIM];
__device__ hf g_vh[(size_t)BATCH * NHEAD * SEQ * HDIM];

// ---------------------------------------------------------------------------
// PTX helpers
// ---------------------------------------------------------------------------
__device__ __forceinline__ uint32_t smem_u32(const void* p) {
    uint32_t a;
    asm("{ .reg .u64 t; cvta.to.shared.u64 t, %1; cvt.u32.u64 %0, t; }" : "=r"(a) : "l"(p));
    return a;
}
#define CP16(sm, gm) asm volatile("cp.async.cg.shared.global [%0], [%1], 16;" :: "r"(sm), "l"(gm))
#define CP_COMMIT()  asm volatile("cp.async.commit_group;" ::: "memory")
#define CP_WAIT2()   asm volatile("cp.async.wait_group 2;" ::: "memory")
#define CP_WAIT1()   asm volatile("cp.async.wait_group 1;" ::: "memory")
#define CP_WAIT0()   asm volatile("cp.async.wait_group 0;" ::: "memory")

__device__ __forceinline__ void ldsm4(uint32_t* r, uint32_t addr) {
    asm volatile("ldmatrix.sync.aligned.m8n8.x4.shared.b16 {%0,%1,%2,%3}, [%4];"
                 : "=r"(r[0]), "=r"(r[1]), "=r"(r[2]), "=r"(r[3]) : "r"(addr));
}
__device__ __forceinline__ void ldsm4t(uint32_t* r, uint32_t addr) {
    asm volatile("ldmatrix.sync.aligned.m8n8.x4.trans.shared.b16 {%0,%1,%2,%3}, [%4];"
                 : "=r"(r[0]), "=r"(r[1]), "=r"(r[2]), "=r"(r[3]) : "r"(addr));
}
__device__ __forceinline__ void mma16816(float* c, const uint32_t* a, const uint32_t* b) {
    asm volatile(
        "mma.sync.aligned.m16n8k16.row.col.f32.f16.f16.f32 "
        "{%0,%1,%2,%3}, {%4,%5,%6,%7}, {%8,%9}, {%0,%1,%2,%3};"
        : "+f"(c[0]), "+f"(c[1]), "+f"(c[2]), "+f"(c[3])
        : "r"(a[0]), "r"(a[1]), "r"(a[2]), "r"(a[3]), "r"(b[0]), "r"(b[1]));
}
__device__ __forceinline__ float ex2(float x) {
    float y;
    asm("ex2.approx.f32 %0, %1;" : "=f"(y) : "f"(x));
    return y;
}
__device__ __forceinline__ uint32_t packhf(float x, float y) {
    __half2 t = __floats2half2_rn(x, y);   // x -> low half
    return *(uint32_t*)&t;
}
__device__ __forceinline__ void split2(float x, float y, uint32_t& h, uint32_t& l) {
    h = packhf(x, y);
    __half2 hh = *(__half2*)&h;
    l = packhf(x - __half2float(__low2half(hh)), y - __half2float(__high2half(hh)));
}

// ---------------------------------------------------------------------------
// Fused pre-pass: x split fp16; W_qkv^T split fp16; W_out^T single fp16.
// ---------------------------------------------------------------------------
__global__ __launch_bounds__(256) void prep_kernel(
    const float* __restrict__ x, const float* __restrict__ Wq,
    const float* __restrict__ Wo,
    hf* __restrict__ xhi, hf* __restrict__ xlo,
    hf* __restrict__ wqh, hf* __restrict__ wql,
    hf* __restrict__ woh)
{
    __shared__ float t[32][33];
    const int blk = blockIdx.x, tid = threadIdx.x;

    if (blk < 4096) {
        int i = blk * 256 + tid;
        float4 v = ((const float4*)x)[i];
        uint32_t h0, l0, h1, l1;
        split2(v.x, v.y, h0, l0);
        split2(v.z, v.w, h1, l1);
        *(uint2*)(xhi + 4 * (size_t)i) = make_uint2(h0, h1);
        *(uint2*)(xlo + 4 * (size_t)i) = make_uint2(l0, l1);
        return;
    }

    const float* W; hf *hi, *lo;
    int K, N, bx, by;
    bool want_lo;
    if (blk < 7168) {
        int idx = blk - 4096;
        W = Wq; hi = wqh; lo = wql; K = DMODEL; N = QKV_N; want_lo = true;
        bx = idx % 96; by = idx / 96;
    } else {
        int idx = blk - 7168;
        W = Wo; hi = woh; lo = nullptr; K = DMODEL; N = DMODEL; want_lo = false;
        bx = idx & 31; by = idx >> 5;
    }
    const int tx = tid & 31, ty = tid >> 5;
    const int n0 = bx * 32, k0 = by * 32;
    #pragma unroll
    for (int i = 0; i < 4; i++)
        t[ty + i * 8][tx] = W[(size_t)(k0 + ty + i * 8) * N + n0 + tx];
    __syncthreads();
    #pragma unroll
    for (int i = 0; i < 4; i++) {
        float v = t[tx][ty + i * 8];
        hf h = __float2half_rn(v);
        size_t o = (size_t)(n0 + ty + i * 8) * K + k0 + tx;
        hi[o] = h;
        if (want_lo) lo[o] = __float2half_rn(v - __half2float(h));
    }
}

// ---------------------------------------------------------------------------
// GEMM common geometry (R11 proven): 512 thr, 16 warps (4x4), warp 32x32,
// CTA 128x128, BK=32, 4-stage cp.async ring, wait2, term-major MMAs.
// ---------------------------------------------------------------------------
#define GK 32
#define GROW 80
#define GSUB (128 * GROW)

// ---- 3-term variant (QKV): A split, B split, drop Al*Bl ----
#define G3STAGE (4 * GSUB)     // Ah|Al|Bh|Bl = 40960
#define G3_DYN (4 * G3STAGE + 256)

__device__ __forceinline__ void gm3_load(
    uint32_t buf, const hf* gah, const hf* gal, const hf* gbh, const hf* gbl,
    int K, int tid)
{
    int row = tid >> 2, col = tid & 3;
    uint32_t so = (uint32_t)(row * GROW + col * 16);
    size_t g = (size_t)row * K + (size_t)col * 8;
    CP16(buf + so,            gah + g);
    CP16(buf + GSUB + so,     gal + g);
    CP16(buf + 2 * GSUB + so, gbh + g);
    CP16(buf + 3 * GSUB + so, gbl + g);
}

__device__ __forceinline__ void g3_ldfr(uint32_t* fr, uint32_t sb,
                                        uint32_t a_off, uint32_t b_off, uint32_t ko)
{
    ldsm4(fr + 0,  sb + a_off + ko);
    ldsm4(fr + 4,  sb + a_off + 16u * GROW + ko);
    ldsm4(fr + 8,  sb + GSUB + a_off + ko);
    ldsm4(fr + 12, sb + GSUB + a_off + 16u * GROW + ko);
    ldsm4(fr + 16, sb + 2u * GSUB + b_off + ko);
    ldsm4(fr + 20, sb + 2u * GSUB + b_off + 16u * GROW + ko);
    ldsm4(fr + 24, sb + 3u * GSUB + b_off + ko);
    ldsm4(fr + 28, sb + 3u * GSUB + b_off + 16u * GROW + ko);
}

__device__ __forceinline__ void g3_mma(float acc[2][4][4], const uint32_t* fr)
{
    const uint32_t* ah = fr;
    const uint32_t* al = fr + 8;
    const uint32_t* bh = fr + 16;
    const uint32_t* bl = fr + 24;
    #pragma unroll
    for (int i = 0; i < 2; i++)
        #pragma unroll
        for (int j = 0; j < 4; j++)
            mma16816(acc[i][j], ah + i * 4, bh + (j >> 1) * 4 + (j & 1) * 2);
    #pragma unroll
    for (int i = 0; i < 2; i++)
        #pragma unroll
        for (int j = 0; j < 4; j++)
            mma16816(acc[i][j], ah + i * 4, bl + (j >> 1) * 4 + (j & 1) * 2);
    #pragma unroll
    for (int i = 0; i < 2; i++)
        #pragma unroll
        for (int j = 0; j < 4; j++)
            mma16816(acc[i][j], al + i * 4, bh + (j >> 1) * 4 + (j & 1) * 2);
}

// QKV GEMM: fused split/scatter epilogue. q split (scaled), k/v single fp16.
__global__ __launch_bounds__(512, 1) void gemm_qkv(
    const hf* __restrict__ Ah, const hf* __restrict__ Al,
    const hf* __restrict__ Bh, const hf* __restrict__ Bl,
    const float* __restrict__ bias,
    hf* __restrict__ oqh, hf* __restrict__ oql,
    hf* __restrict__ okh, hf* __restrict__ ovh,
    int M, int N, int K)
{
    extern __shared__ __align__(128) char dynsm[];
    const uint32_t smbase = smem_u32(dynsm);

    const int tid = threadIdx.x;
    const int wid = tid >> 5, lane = tid & 31;
    const int wr = wid >> 2, wc = wid & 3;
    const int m0 = blockIdx.y * 128, n0 = blockIdx.x * 128;

    const hf* ah0 = Ah + (size_t)m0 * K;
    const hf* al0 = Al + (size_t)m0 * K;
    const hf* bh0 = Bh + (size_t)n0 * K;
    const hf* bl0 = Bl + (size_t)n0 * K;

    const uint32_t a_off = (uint32_t)((wr * 32 + (lane & 15)) * GROW + (lane >> 4) * 16);
    const uint32_t b_off = (uint32_t)((wc * 32 + (lane >> 4) * 8 + (lane & 7)) * GROW
                                      + (((lane & 15) >> 3) * 16));

    float acc[2][4][4];
    #pragma unroll
    for (int i = 0; i < 2; i++)
        #pragma unroll
        for (int j = 0; j < 4; j++)
            #pragma unroll
            for (int r = 0; r < 4; r++) acc[i][j][r] = 0.f;

    const int NS = K / GK;

    gm3_load(smbase,               ah0,          al0,          bh0,          bl0,          K, tid);
    CP_COMMIT();
    gm3_load(smbase + G3STAGE,     ah0 + GK,     al0 + GK,     bh0 + GK,     bl0 + GK,     K, tid);
    CP_COMMIT();
    gm3_load(smbase + 2 * G3STAGE, ah0 + 2 * GK, al0 + 2 * GK, bh0 + 2 * GK, bl0 + 2 * GK, K, tid);
    CP_COMMIT();

    for (int s = 0; s < NS; s++) {
        CP_WAIT2();
        __syncthreads();

        const uint32_t sb = smbase + (uint32_t)(s & 3) * G3STAGE;
        uint32_t f0[32], f1[32];
        g3_ldfr(f0, sb, a_off, b_off, 0);

        int t = s + 3;
        if (t < NS)
            gm3_load(smbase + (uint32_t)(t & 3) * G3STAGE,
                     ah0 + (size_t)t * GK, al0 + (size_t)t * GK,
                     bh0 + (size_t)t * GK, bl0 + (size_t)t * GK, K, tid);
        CP_COMMIT();

        g3_ldfr(f1, sb, a_off, b_off, 32);
        g3_mma(acc, f0);
        g3_mma(acc, f1);
    }

    const int er = m0 + wr * 32 + (lane >> 2);
    const int ec = n0 + wc * 32 + 2 * (lane & 3);
    const int part = ec >> 10;
    // q scale folded in LOG2 domain: 1/sqrt(64) * log2(e)
    const float sc = (part == 0) ? 0.18033688f : 1.0f;
    #pragma unroll
    for (int i = 0; i < 2; i++)
        #pragma unroll
        for (int j = 0; j < 4; j++) {
            int r = er + i * 16, c = ec + j * 8;
            int hh = (c >> 6) & 15, d = c & 63;
            float b0 = bias[c], b1 = bias[c + 1];
            float v0 = (acc[i][j][0] + b0) * sc, v1 = (acc[i][j][1] + b1) * sc;
            float v2 = (acc[i][j][2] + b0) * sc, v3 = (acc[i][j][3] + b1) * sc;
            size_t off  = (((size_t)(r >> 11) * NHEAD + hh) * SEQ + (r & 2047)) * HDIM + d;
            int r2 = r + 8;
            size_t off2 = (((size_t)(r2 >> 11) * NHEAD + hh) * SEQ + (r2 & 2047)) * HDIM + d;
            if (part == 0) {
                uint32_t ph, pl;
                split2(v0, v1, ph, pl);
                *(uint32_t*)(oqh + off) = ph;
                *(uint32_t*)(oql + off) = pl;
                split2(v2, v3, ph, pl);
                *(uint32_t*)(oqh + off2) = ph;
                *(uint32_t*)(oql + off2) = pl;
            } else {
                hf* dst = (part == 1) ? okh : ovh;
                *(uint32_t*)(dst + off)  = packhf(v0, v1);
                *(uint32_t*)(dst + off2) = packhf(v2, v3);
            }
        }
}

// ---- 2-term variant (out-proj): A split, B single ----
#define G2STAGE (3 * GSUB)     // Ah|Al|B = 30720
#define G2_DYN (4 * G2STAGE + 256)

__device__ __forceinline__ void gm2_load(
    uint32_t buf, const hf* gah, const hf* gal, const hf* gb, int K, int tid)
{
    int row = tid >> 2, col = tid & 3;
    uint32_t so = (uint32_t)(row * GROW + col * 16);
    size_t g = (size_t)row * K + (size_t)col * 8;
    CP16(buf + so,            gah + g);
    CP16(buf + GSUB + so,     gal + g);
    CP16(buf + 2 * GSUB + so, gb + g);
}

__device__ __forceinline__ void g2_ldfr(uint32_t* fr, uint32_t sb,
                                        uint32_t a_off, uint32_t b_off, uint32_t ko)
{
    ldsm4(fr + 0,  sb + a_off + ko);
    ldsm4(fr + 4,  sb + a_off + 16u * GROW + ko);
    ldsm4(fr + 8,  sb + GSUB + a_off + ko);
    ldsm4(fr + 12, sb + GSUB + a_off + 16u * GROW + ko);
    ldsm4(fr + 16, sb + 2u * GSUB + b_off + ko);
    ldsm4(fr + 20, sb + 2u * GSUB + b_off + 16u * GROW + ko);
}

__device__ __forceinline__ void g2_mma(float acc[2][4][4], const uint32_t* fr)
{
    const uint32_t* ah = fr;
    const uint32_t* al = fr + 8;
    const uint32_t* b  = fr + 16;
    #pragma unroll
    for (int i = 0; i < 2; i++)
        #pragma unroll
        for (int j = 0; j < 4; j++)
            mma16816(acc[i][j], ah + i * 4, b + (j >> 1) * 4 + (j & 1) * 2);
    #pragma unroll
    for (int i = 0; i < 2; i++)
        #pragma unroll
        for (int j = 0; j < 4; j++)
            mma16816(acc[i][j], al + i * 4, b + (j >> 1) * 4 + (j & 1) * 2);
}

__global__ __launch_bounds__(512, 1) void gemm_out(
    const hf* __restrict__ Ah, const hf* __restrict__ Al,
    const hf* __restrict__ B, float* __restrict__ C,
    int M, int N, int K)
{
    extern __shared__ __align__(128) char dynsm[];
    const uint32_t smbase = smem_u32(dynsm);

    const int tid = threadIdx.x;
    const int wid = tid >> 5, lane = tid & 31;
    const int wr = wid >> 2, wc = wid & 3;
    const int m0 = blockIdx.y * 128, n0 = blockIdx.x * 128;

    const hf* ah0 = Ah + (size_t)m0 * K;
    const hf* al0 = Al + (size_t)m0 * K;
    const hf* b0p = B + (size_t)n0 * K;

    const uint32_t a_off = (uint32_t)((wr * 32 + (lane & 15)) * GROW + (lane >> 4) * 16);
    const uint32_t b_off = (uint32_t)((wc * 32 + (lane >> 4) * 8 + (lane & 7)) * GROW
                                      + (((lane & 15) >> 3) * 16));

    float acc[2][4][4];
    #pragma unroll
    for (int i = 0; i < 2; i++)
        #pragma unroll
        for (int j = 0; j < 4; j++)
            #pragma unroll
            for (int r = 0; r < 4; r++) acc[i][j][r] = 0.f;

    const int NS = K / GK;

    gm2_load(smbase,               ah0,          al0,          b0p,          K, tid);
    CP_COMMIT();
    gm2_load(smbase + G2STAGE,     ah0 + GK,     al0 + GK,     b0p + GK,     K, tid);
    CP_COMMIT();
    gm2_load(smbase + 2 * G2STAGE, ah0 + 2 * GK, al0 + 2 * GK, b0p + 2 * GK, K, tid);
    CP_COMMIT();

    for (int s = 0; s < NS; s++) {
        CP_WAIT2();
        __syncthreads();

        const uint32_t sb = smbase + (uint32_t)(s & 3) * G2STAGE;
        uint32_t f0[24], f1[24];
        g2_ldfr(f0, sb, a_off, b_off, 0);

        int t = s + 3;
        if (t < NS)
            gm2_load(smbase + (uint32_t)(t & 3) * G2STAGE,
                     ah0 + (size_t)t * GK, al0 + (size_t)t * GK,
                     b0p + (size_t)t * GK, K, tid);
        CP_COMMIT();

        g2_ldfr(f1, sb, a_off, b_off, 32);
        g2_mma(acc, f0);
        g2_mma(acc, f1);
    }

    const int er = m0 + wr * 32 + (lane >> 2);
    const int ec = n0 + wc * 32 + 2 * (lane & 3);
    #pragma unroll
    for (int i = 0; i < 2; i++)
        #pragma unroll
        for (int j = 0; j < 4; j++) {
            int r = er + i * 16, c = ec + j * 8;
            *(float2*)(C + (size_t)r * N + c) =
                make_float2(acc[i][j][0], acc[i][j][1]);
            *(float2*)(C + (size_t)(r + 8) * N + c) =
                make_float2(acc[i][j][2], acc[i][j][3]);
        }
}

// ---------------------------------------------------------------------------
// HMMA flash attention, fp16 2-term: Q split, K single; P split, V single.
// CTA = 128 q rows x one (b,h); 8 warps, warp = 16 q x 64 keys.
// ---------------------------------------------------------------------------
#define AROW 144
#define AQ_BYTES (128 * AROW)
#define AKV_BYTES (64 * AROW)
#define AST (2 * AKV_BYTES)                  // kh | vh
#define ATT_SMEM (2 * AQ_BYTES + 3 * AST)    // 36864 + 55296 = 92160

__device__ __forceinline__ void att_load_kv(
    uint32_t base, const hf* khp, const hf* vhp, int kt, int tid)
{
    #pragma unroll
    for (int i = 0; i < 2; i++) {
        int c = i * 256 + tid;
        int row = c >> 3, col = c & 7;
        uint32_t so = (uint32_t)(row * AROW + col * 16);
        size_t g = (size_t)(kt * 64 + row) * HDIM + col * 8;
        CP16(base + so,             khp + g);
        CP16(base + AKV_BYTES + so, vhp + g);
    }
}

__device__ __forceinline__ void ld_kfr(uint32_t* f, uint32_t kvb, uint32_t kb_off, int ks)
{
    #pragma unroll
    for (int g = 0; g < 4; g++)
        ldsm4(f + g * 4, kvb + kb_off + (uint32_t)(g * 16 * AROW) + (uint32_t)(ks * 32));
}
__device__ __forceinline__ void ld_vfr(uint32_t* f, uint32_t kvb, uint32_t vb_off, int ks)
{
    #pragma unroll
    for (int g = 0; g < 4; g++)
        ldsm4t(f + g * 4, kvb + AKV_BYTES + vb_off
                        + (uint32_t)(ks * 16 * AROW) + (uint32_t)(g * 32));
}

__global__ __launch_bounds__(256) void flash_hmma(
    const hf* __restrict__ qh, const hf* __restrict__ ql,
    const hf* __restrict__ kh, const hf* __restrict__ vh,
    hf* __restrict__ chi, hf* __restrict__ clo)
{
    extern __shared__ __align__(128) char asmbuf[];
    const uint32_t sb = smem_u32(asmbuf);
    const int tid = threadIdx.x, wid = tid >> 5, lane = tid & 31;
    const int qt = 15 - (int)blockIdx.x;
    const int h = blockIdx.y, b = blockIdx.z;
    const int q0 = qt * 128;
    const int ktmax = 2 * qt + 1;

    const size_t headoff = ((size_t)b * NHEAD + h) * SEQ * HDIM;
    const hf* qhp = qh + headoff + (size_t)q0 * HDIM;
    const hf* qlp = ql + headoff + (size_t)q0 * HDIM;
    const hf* khp = kh + headoff;
    const hf* vhp = vh + headoff;

    #pragma unroll
    for (int i = 0; i < 4; i++) {
        int c = i * 256 + tid;
        int row = c >> 3, col = c & 7;
        uint32_t so = (uint32_t)(row * AROW + col * 16);
        size_t g = (size_t)row * HDIM + col * 8;
        CP16(sb + so,            qhp + g);
        CP16(sb + AQ_BYTES + so, qlp + g);
    }
    att_load_kv(sb + 2 * AQ_BYTES, khp, vhp, 0, tid);
    CP_COMMIT();
    att_load_kv(sb + 2 * AQ_BYTES + AST, khp, vhp, 1, tid);
    CP_COMMIT();

    float s[8][4], acc[8][4];
    float m0v = -1e30f, m1v = -1e30f, l0v = 0.f, l1v = 0.f;
    #pragma unroll
    for (int nc = 0; nc < 8; nc++) {
        acc[nc][0] = acc[nc][1] = acc[nc][2] = acc[nc][3] = 0.f;
    }
    uint32_t qfh[16], qfl[16];

    const uint32_t a_off = (uint32_t)((wid * 16 + (lane & 15)) * AROW + (lane >> 4) * 16);
    const uint32_t kb_off = (uint32_t)(((lane >> 4) * 8 + (lane & 7)) * AROW
                                       + (((lane & 15) >> 3) * 16));
    const uint32_t vb_off = (uint32_t)((lane & 15) * AROW + (lane >> 4) * 16);

    for (int kt = 0; kt <= ktmax; kt++) {
        if (kt < ktmax) { CP_WAIT1(); } else { CP_WAIT0(); }
        __syncthreads();

        if (kt == 0) {
            #pragma unroll
            for (int ks = 0; ks < 4; ks++) {
                ldsm4(&qfh[ks * 4], sb + a_off + (uint32_t)(ks * 32));
                ldsm4(&qfl[ks * 4], sb + AQ_BYTES + a_off + (uint32_t)(ks * 32));
            }
        }
        int t = kt + 2;
        if (t <= ktmax) {
            att_load_kv(sb + 2 * AQ_BYTES + (uint32_t)(t % 3) * AST, khp, vhp, t, tid);
            CP_COMMIT();
        }
        const uint32_t kvb = sb + 2 * AQ_BYTES + (uint32_t)(kt % 3) * AST;

        // ---- scores = Q K^T (2-term: qh*K + ql*K) ----
        #pragma unroll
        for (int nc = 0; nc < 8; nc++) {
            s[nc][0] = s[nc][1] = s[nc][2] = s[nc][3] = 0.f;
        }
        {
            uint32_t kfb[2][16];
            ld_kfr(kfb[0], kvb, kb_off, 0);
            #pragma unroll
            for (int ks = 0; ks < 4; ks++) {
                if (ks < 3) ld_kfr(kfb[(ks + 1) & 1], kvb, kb_off, ks + 1);
                const uint32_t* kf = kfb[ks & 1];
                #pragma unroll
                for (int nc = 0; nc < 8; nc++)
                    mma16816(s[nc], &qfh[ks * 4], kf + (nc >> 1) * 4 + (nc & 1) * 2);
                #pragma unroll
                for (int nc = 0; nc < 8; nc++)
                    mma16816(s[nc], &qfl[ks * 4], kf + (nc >> 1) * 4 + (nc & 1) * 2);
            }
        }

        // ---- online softmax (log2 domain; scores pre-scaled by log2e/8) ----
        if (kt >= 2 * qt) {
            const int keyb = kt * 64 + 2 * (lane & 3);
            const int r0 = q0 + wid * 16 + (lane >> 2);
            #pragma unroll
            for (int nc = 0; nc < 8; nc++) {
                int k0 = keyb + nc * 8;
                if (k0     > r0)     s[nc][0] = -1e30f;
                if (k0 + 1 > r0)     s[nc][1] = -1e30f;
                if (k0     > r0 + 8) s[nc][2] = -1e30f;
                if (k0 + 1 > r0 + 8) s[nc][3] = -1e30f;
            }
        }
        float mx0 = -1e30f, mx1 = -1e30f;
        #pragma unroll
        for (int nc = 0; nc < 8; nc++) {
            mx0 = fmaxf(mx0, fmaxf(s[nc][0], s[nc][1]));
            mx1 = fmaxf(mx1, fmaxf(s[nc][2], s[nc][3]));
        }
        mx0 = fmaxf(mx0, __shfl_xor_sync(0xffffffffu, mx0, 1));
        mx0 = fmaxf(mx0, __shfl_xor_sync(0xffffffffu, mx0, 2));
        mx1 = fmaxf(mx1, __shfl_xor_sync(0xffffffffu, mx1, 1));
        mx1 = fmaxf(mx1, __shfl_xor_sync(0xffffffffu, mx1, 2));
        float mn0 = fmaxf(m0v, mx0), mn1 = fmaxf(m1v, mx1);
        float c0 = ex2(m0v - mn0), c1 = ex2(m1v - mn1);
        float su0 = 0.f, su1 = 0.f;
        #pragma unroll
        for (int nc = 0; nc < 8; nc++) {
            s[nc][0] = ex2(s[nc][0] - mn0);
            s[nc][1] = ex2(s[nc][1] - mn0);
            s[nc][2] = ex2(s[nc][2] - mn1);
            s[nc][3] = ex2(s[nc][3] - mn1);
            su0 += s[nc][0] + s[nc][1];
            su1 += s[nc][2] + s[nc][3];
        }
        su0 += __shfl_xor_sync(0xffffffffu, su0, 1);
        su0 += __shfl_xor_sync(0xffffffffu, su0, 2);
        su1 += __shfl_xor_sync(0xffffffffu, su1, 1);
        su1 += __shfl_xor_sync(0xffffffffu, su1, 2);
        l0v = l0v * c0 + su0;
        l1v = l1v * c1 + su1;
        m0v = mn0; m1v = mn1;
        #pragma unroll
        for (int nc = 0; nc < 8; nc++) {
            acc[nc][0] *= c0; acc[nc][1] *= c0;
            acc[nc][2] *= c1; acc[nc][3] *= c1;
        }

        // ---- ctx += P V (2-term: ph*V + pl*V) ----
        {
            uint32_t vfb[2][16];
            ld_vfr(vfb[0], kvb, vb_off, 0);
            #pragma unroll
            for (int ks = 0; ks < 4; ks++) {
                if (ks < 3) ld_vfr(vfb[(ks + 1) & 1], kvb, vb_off, ks + 1);
                uint32_t ph[4], pl[4];
                split2(s[2 * ks][0],     s[2 * ks][1],     ph[0], pl[0]);
                split2(s[2 * ks][2],     s[2 * ks][3],     ph[1], pl[1]);
                split2(s[2 * ks + 1][0], s[2 * ks + 1][1], ph[2], pl[2]);
                split2(s[2 * ks + 1][2], s[2 * ks + 1][3], ph[3], pl[3]);
                const uint32_t* vf = vfb[ks & 1];
                #pragma unroll
                for (int nc = 0; nc < 8; nc++)
                    mma16816(acc[nc], ph, vf + (nc >> 1) * 4 + (nc & 1) * 2);
                #pragma unroll
                for (int nc = 0; nc < 8; nc++)
                    mma16816(acc[nc], pl, vf + (nc >> 1) * 4 + (nc & 1) * 2);
            }
        }
    }

    float i0 = 1.f / l0v, i1 = 1.f / l1v;
    const int r0 = q0 + wid * 16 + (lane >> 2);
    const int cb = h * HDIM + 2 * (lane & 3);
    #pragma unroll
    for (int nc = 0; nc < 8; nc++) {
        int cc = cb + nc * 8;
        uint32_t ph, pl;
        split2(acc[nc][0] * i0, acc[nc][1] * i0, ph, pl);
        size_t off = (size_t)(b * SEQ + r0) * DMODEL + cc;
        *(uint32_t*)(chi + off) = ph;
        *(uint32_t*)(clo + off) = pl;
        split2(acc[nc][2] * i1, acc[nc][3] * i1, ph, pl);
        off = (size_t)(b * SEQ + r0 + 8) * DMODEL + cc;
        *(uint32_t*)(chi + off) = ph;
        *(uint32_t*)(clo + off) = pl;
    }
}

// ---------------------------------------------------------------------------
extern "C" void kernel_launch(void* const* d_in, const int* in_sizes, int n_in,
                              void* d_out, int out_size)
{
    (void)in_sizes; (void)n_in; (void)out_size;
    const float* x     = (const float*)d_in[0];
    const float* W_qkv = (const float*)d_in[1];
    const float* b_qkv = (const float*)d_in[2];
    const float* W_out = (const float*)d_in[3];
    float* out = (float*)d_out;

    hf *xhi, *xlo, *wqh, *wql, *woh, *chi, *clo;
    hf *qh, *ql, *kh, *vh;
    cudaGetSymbolAddress((void**)&xhi, g_xhi);
    cudaGetSymbolAddress((void**)&xlo, g_xlo);
    cudaGetSymbolAddress((void**)&wqh, g_wqh);
    cudaGetSymbolAddress((void**)&wql, g_wql);
    cudaGetSymbolAddress((void**)&woh, g_woh);
    cudaGetSymbolAddress((void**)&chi, g_chi);
    cudaGetSymbolAddress((void**)&clo, g_clo);
    cudaGetSymbolAddress((void**)&qh, g_qh);
    cudaGetSymbolAddress((void**)&ql, g_ql);
    cudaGetSymbolAddress((void**)&kh, g_kh);
    cudaGetSymbolAddress((void**)&vh, g_vh);

    cudaFuncSetAttribute(gemm_qkv, cudaFuncAttributeMaxDynamicSharedMemorySize, G3_DYN);
    cudaFuncSetAttribute(gemm_out, cudaFuncAttributeMaxDynamicSharedMemorySize, G2_DYN);
    cudaFuncSetAttribute(flash_hmma, cudaFuncAttributeMaxDynamicSharedMemorySize, ATT_SMEM);

    // fused pre-pass (one launch)
    prep_kernel<<<8192, 256>>>(x, W_qkv, W_out, xhi, xlo, wqh, wql, woh);

    gemm_qkv<<<dim3(QKV_N / 128, ROWS / 128), 512, G3_DYN>>>(
        xhi, xlo, wqh, wql, b_qkv, qh, ql, kh, vh, ROWS, QKV_N, DMODEL);

    flash_hmma<<<dim3(16, NHEAD, BATCH), 256, ATT_SMEM>>>(
        qh, ql, kh, vh, chi, clo);

    gemm_out<<<dim3(DMODEL / 128, ROWS / 128), 512, G2_DYN>>>(
        chi, clo, woh, out, ROWS, DMODEL, DMODEL);
}

// round 15
// speedup vs baseline: 1.6158x; 1.2440x over previous
#include <cuda_runtime.h>
#include <cuda_fp16.h>
#include <math.h>
#include <stdint.h>

#define BATCH 2
#define SEQ   2048
#define DMODEL 1024
#define NHEAD 16
#define HDIM  64
#define ROWS  (BATCH*SEQ)          // 4096
#define QKV_N (3*DMODEL)           // 3072

typedef __half hf;

// ---------------------------------------------------------------------------
// Device scratch (fp16)
// ---------------------------------------------------------------------------
__device__ hf g_xhi[(size_t)ROWS * DMODEL];
__device__ hf g_xlo[(size_t)ROWS * DMODEL];
__device__ hf g_wqh[(size_t)QKV_N * DMODEL];   // W_qkv^T single fp16
__device__ hf g_woh[(size_t)DMODEL * DMODEL];  // W_out^T single fp16
__device__ hf g_chi[(size_t)ROWS * DMODEL];    // ctx single fp16
// q split; k, v single fp16. layout [b][h][s][d]
__device__ hf g_qh[(size_t)BATCH * NHEAD * SEQ * HDIM];
__device__ hf g_ql[(size_t)BATCH * NHEAD * SEQ * HDIM];
__device__ hf g_kh[(size_t)BATCH * NHEAD * SEQ * HDIM];
__device__ hf g_vh[(size_t)BATCH * NHEAD * SEQ * HDIM];

// ---------------------------------------------------------------------------
// PTX helpers
// ---------------------------------------------------------------------------
__device__ __forceinline__ uint32_t smem_u32(const void* p) {
    uint32_t a;
    asm("{ .reg .u64 t; cvta.to.shared.u64 t, %1; cvt.u32.u64 %0, t; }" : "=r"(a) : "l"(p));
    return a;
}
#define CP16(sm, gm) asm volatile("cp.async.cg.shared.global [%0], [%1], 16;" :: "r"(sm), "l"(gm))
#define CP_COMMIT()  asm volatile("cp.async.commit_group;" ::: "memory")
#define CP_WAIT2()   asm volatile("cp.async.wait_group 2;" ::: "memory")
#define CP_WAIT1()   asm volatile("cp.async.wait_group 1;" ::: "memory")
#define CP_WAIT0()   asm volatile("cp.async.wait_group 0;" ::: "memory")

__device__ __forceinline__ void ldsm4(uint32_t* r, uint32_t addr) {
    asm volatile("ldmatrix.sync.aligned.m8n8.x4.shared.b16 {%0,%1,%2,%3}, [%4];"
                 : "=r"(r[0]), "=r"(r[1]), "=r"(r[2]), "=r"(r[3]) : "r"(addr));
}
__device__ __forceinline__ void ldsm4t(uint32_t* r, uint32_t addr) {
    asm volatile("ldmatrix.sync.aligned.m8n8.x4.trans.shared.b16 {%0,%1,%2,%3}, [%4];"
                 : "=r"(r[0]), "=r"(r[1]), "=r"(r[2]), "=r"(r[3]) : "r"(addr));
}
__device__ __forceinline__ void mma16816(float* c, const uint32_t* a, const uint32_t* b) {
    asm volatile(
        "mma.sync.aligned.m16n8k16.row.col.f32.f16.f16.f32 "
        "{%0,%1,%2,%3}, {%4,%5,%6,%7}, {%8,%9}, {%0,%1,%2,%3};"
        : "+f"(c[0]), "+f"(c[1]), "+f"(c[2]), "+f"(c[3])
        : "r"(a[0]), "r"(a[1]), "r"(a[2]), "r"(a[3]), "r"(b[0]), "r"(b[1]));
}
__device__ __forceinline__ float ex2(float x) {
    float y;
    asm("ex2.approx.f32 %0, %1;" : "=f"(y) : "f"(x));
    return y;
}
__device__ __forceinline__ uint32_t packhf(float x, float y) {
    __half2 t = __floats2half2_rn(x, y);   // x -> low half
    return *(uint32_t*)&t;
}
__device__ __forceinline__ void split2(float x, float y, uint32_t& h, uint32_t& l) {
    h = packhf(x, y);
    __half2 hh = *(__half2*)&h;
    l = packhf(x - __half2float(__low2half(hh)), y - __half2float(__high2half(hh)));
}

// ---------------------------------------------------------------------------
// Fused pre-pass: x split fp16; W_qkv^T and W_out^T single fp16.
// ---------------------------------------------------------------------------
__global__ __launch_bounds__(256) void prep_kernel(
    const float* __restrict__ x, const float* __restrict__ Wq,
    const float* __restrict__ Wo,
    hf* __restrict__ xhi, hf* __restrict__ xlo,
    hf* __restrict__ wqh, hf* __restrict__ woh)
{
    __shared__ float t[32][33];
    const int blk = blockIdx.x, tid = threadIdx.x;

    if (blk < 4096) {
        int i = blk * 256 + tid;
        float4 v = ((const float4*)x)[i];
        uint32_t h0, l0, h1, l1;
        split2(v.x, v.y, h0, l0);
        split2(v.z, v.w, h1, l1);
        *(uint2*)(xhi + 4 * (size_t)i) = make_uint2(h0, h1);
        *(uint2*)(xlo + 4 * (size_t)i) = make_uint2(l0, l1);
        return;
    }

    const float* W; hf* hi;
    int K, N, bx, by;
    if (blk < 7168) {
        int idx = blk - 4096;
        W = Wq; hi = wqh; K = DMODEL; N = QKV_N;
        bx = idx % 96; by = idx / 96;
    } else {
        int idx = blk - 7168;
        W = Wo; hi = woh; K = DMODEL; N = DMODEL;
        bx = idx & 31; by = idx >> 5;
    }
    const int tx = tid & 31, ty = tid >> 5;
    const int n0 = bx * 32, k0 = by * 32;
    #pragma unroll
    for (int i = 0; i < 4; i++)
        t[ty + i * 8][tx] = W[(size_t)(k0 + ty + i * 8) * N + n0 + tx];
    __syncthreads();
    #pragma unroll
    for (int i = 0; i < 4; i++) {
        float v = t[tx][ty + i * 8];
        size_t o = (size_t)(n0 + ty + i * 8) * K + k0 + tx;
        hi[o] = __float2half_rn(v);
    }
}

// ---------------------------------------------------------------------------
// GEMM common geometry (R11 proven): 512 thr, 16 warps (4x4), warp 32x32,
// CTA 128x128, BK=32, 4-stage cp.async ring, wait2, term-major MMAs.
// ---------------------------------------------------------------------------
#define GK 32
#define GROW 80
#define GSUB (128 * GROW)

// ---- 2-term QKV GEMM: A split (x), B single (W_qkv) ----
#define G2STAGE (3 * GSUB)     // Ah|Al|B = 30720
#define G2_DYN (4 * G2STAGE + 256)

__device__ __forceinline__ void gm2_load(
    uint32_t buf, const hf* gah, const hf* gal, const hf* gb, int K, int tid)
{
    int row = tid >> 2, col = tid & 3;
    uint32_t so = (uint32_t)(row * GROW + col * 16);
    size_t g = (size_t)row * K + (size_t)col * 8;
    CP16(buf + so,            gah + g);
    CP16(buf + GSUB + so,     gal + g);
    CP16(buf + 2 * GSUB + so, gb + g);
}

__device__ __forceinline__ void g2_ldfr(uint32_t* fr, uint32_t sb,
                                        uint32_t a_off, uint32_t b_off, uint32_t ko)
{
    ldsm4(fr + 0,  sb + a_off + ko);
    ldsm4(fr + 4,  sb + a_off + 16u * GROW + ko);
    ldsm4(fr + 8,  sb + GSUB + a_off + ko);
    ldsm4(fr + 12, sb + GSUB + a_off + 16u * GROW + ko);
    ldsm4(fr + 16, sb + 2u * GSUB + b_off + ko);
    ldsm4(fr + 20, sb + 2u * GSUB + b_off + 16u * GROW + ko);
}

__device__ __forceinline__ void g2_mma(float acc[2][4][4], const uint32_t* fr)
{
    const uint32_t* ah = fr;
    const uint32_t* al = fr + 8;
    const uint32_t* b  = fr + 16;
    #pragma unroll
    for (int i = 0; i < 2; i++)
        #pragma unroll
        for (int j = 0; j < 4; j++)
            mma16816(acc[i][j], ah + i * 4, b + (j >> 1) * 4 + (j & 1) * 2);
    #pragma unroll
    for (int i = 0; i < 2; i++)
        #pragma unroll
        for (int j = 0; j < 4; j++)
            mma16816(acc[i][j], al + i * 4, b + (j >> 1) * 4 + (j & 1) * 2);
}

__global__ __launch_bounds__(512, 1) void gemm_qkv(
    const hf* __restrict__ Ah, const hf* __restrict__ Al,
    const hf* __restrict__ B, const float* __restrict__ bias,
    hf* __restrict__ oqh, hf* __restrict__ oql,
    hf* __restrict__ okh, hf* __restrict__ ovh,
    int M, int N, int K)
{
    extern __shared__ __align__(128) char dynsm[];
    const uint32_t smbase = smem_u32(dynsm);

    const int tid = threadIdx.x;
    const int wid = tid >> 5, lane = tid & 31;
    const int wr = wid >> 2, wc = wid & 3;
    const int m0 = blockIdx.y * 128, n0 = blockIdx.x * 128;

    const hf* ah0 = Ah + (size_t)m0 * K;
    const hf* al0 = Al + (size_t)m0 * K;
    const hf* b0p = B + (size_t)n0 * K;

    const uint32_t a_off = (uint32_t)((wr * 32 + (lane & 15)) * GROW + (lane >> 4) * 16);
    const uint32_t b_off = (uint32_t)((wc * 32 + (lane >> 4) * 8 + (lane & 7)) * GROW
                                      + (((lane & 15) >> 3) * 16));

    float acc[2][4][4];
    #pragma unroll
    for (int i = 0; i < 2; i++)
        #pragma unroll
        for (int j = 0; j < 4; j++)
            #pragma unroll
            for (int r = 0; r < 4; r++) acc[i][j][r] = 0.f;

    const int NS = K / GK;

    gm2_load(smbase,               ah0,          al0,          b0p,          K, tid);
    CP_COMMIT();
    gm2_load(smbase + G2STAGE,     ah0 + GK,     al0 + GK,     b0p + GK,     K, tid);
    CP_COMMIT();
    gm2_load(smbase + 2 * G2STAGE, ah0 + 2 * GK, al0 + 2 * GK, b0p + 2 * GK, K, tid);
    CP_COMMIT();

    for (int s = 0; s < NS; s++) {
        CP_WAIT2();
        __syncthreads();

        const uint32_t sb = smbase + (uint32_t)(s & 3) * G2STAGE;
        uint32_t f0[24], f1[24];
        g2_ldfr(f0, sb, a_off, b_off, 0);

        int t = s + 3;
        if (t < NS)
            gm2_load(smbase + (uint32_t)(t & 3) * G2STAGE,
                     ah0 + (size_t)t * GK, al0 + (size_t)t * GK,
                     b0p + (size_t)t * GK, K, tid);
        CP_COMMIT();

        g2_ldfr(f1, sb, a_off, b_off, 32);
        g2_mma(acc, f0);
        g2_mma(acc, f1);
    }

    const int er = m0 + wr * 32 + (lane >> 2);
    const int ec = n0 + wc * 32 + 2 * (lane & 3);
    const int part = ec >> 10;
    // q scale folded in LOG2 domain: 1/sqrt(64) * log2(e)
    const float sc = (part == 0) ? 0.18033688f : 1.0f;
    #pragma unroll
    for (int i = 0; i < 2; i++)
        #pragma unroll
        for (int j = 0; j < 4; j++) {
            int r = er + i * 16, c = ec + j * 8;
            int hh = (c >> 6) & 15, d = c & 63;
            float b0 = bias[c], b1 = bias[c + 1];
            float v0 = (acc[i][j][0] + b0) * sc, v1 = (acc[i][j][1] + b1) * sc;
            float v2 = (acc[i][j][2] + b0) * sc, v3 = (acc[i][j][3] + b1) * sc;
            size_t off  = (((size_t)(r >> 11) * NHEAD + hh) * SEQ + (r & 2047)) * HDIM + d;
            int r2 = r + 8;
            size_t off2 = (((size_t)(r2 >> 11) * NHEAD + hh) * SEQ + (r2 & 2047)) * HDIM + d;
            if (part == 0) {
                uint32_t ph, pl;
                split2(v0, v1, ph, pl);
                *(uint32_t*)(oqh + off) = ph;
                *(uint32_t*)(oql + off) = pl;
                split2(v2, v3, ph, pl);
                *(uint32_t*)(oqh + off2) = ph;
                *(uint32_t*)(oql + off2) = pl;
            } else {
                hf* dst = (part == 1) ? okh : ovh;
                *(uint32_t*)(dst + off)  = packhf(v0, v1);
                *(uint32_t*)(dst + off2) = packhf(v2, v3);
            }
        }
}

// ---- 1-term out-proj GEMM: A single (ctx), B single (W_out) ----
#define G1STAGE (2 * GSUB)     // A|B = 20480
#define G1_DYN (4 * G1STAGE + 256)

__device__ __forceinline__ void gm1_load(
    uint32_t buf, const hf* ga, const hf* gb, int K, int tid)
{
    int row = tid >> 2, col = tid & 3;
    uint32_t so = (uint32_t)(row * GROW + col * 16);
    size_t g = (size_t)row * K + (size_t)col * 8;
    CP16(buf + so,        ga + g);
    CP16(buf + GSUB + so, gb + g);
}

__device__ __forceinline__ void g1_ldfr(uint32_t* fr, uint32_t sb,
                                        uint32_t a_off, uint32_t b_off, uint32_t ko)
{
    ldsm4(fr + 0,  sb + a_off + ko);
    ldsm4(fr + 4,  sb + a_off + 16u * GROW + ko);
    ldsm4(fr + 8,  sb + GSUB + b_off + ko);
    ldsm4(fr + 12, sb + GSUB + b_off + 16u * GROW + ko);
}

__device__ __forceinline__ void g1_mma(float acc[2][4][4], const uint32_t* fr)
{
    const uint32_t* a = fr;
    const uint32_t* b = fr + 8;
    #pragma unroll
    for (int i = 0; i < 2; i++)
        #pragma unroll
        for (int j = 0; j < 4; j++)
            mma16816(acc[i][j], a + i * 4, b + (j >> 1) * 4 + (j & 1) * 2);
}

__global__ __launch_bounds__(512, 1) void gemm_out(
    const hf* __restrict__ A, const hf* __restrict__ B, float* __restrict__ C,
    int M, int N, int K)
{
    extern __shared__ __align__(128) char dynsm[];
    const uint32_t smbase = smem_u32(dynsm);

    const int tid = threadIdx.x;
    const int wid = tid >> 5, lane = tid & 31;
    const int wr = wid >> 2, wc = wid & 3;
    const int m0 = blockIdx.y * 128, n0 = blockIdx.x * 128;

    const hf* a0p = A + (size_t)m0 * K;
    const hf* b0p = B + (size_t)n0 * K;

    const uint32_t a_off = (uint32_t)((wr * 32 + (lane & 15)) * GROW + (lane >> 4) * 16);
    const uint32_t b_off = (uint32_t)((wc * 32 + (lane >> 4) * 8 + (lane & 7)) * GROW
                                      + (((lane & 15) >> 3) * 16));

    float acc[2][4][4];
    #pragma unroll
    for (int i = 0; i < 2; i++)
        #pragma unroll
        for (int j = 0; j < 4; j++)
            #pragma unroll
            for (int r = 0; r < 4; r++) acc[i][j][r] = 0.f;

    const int NS = K / GK;

    gm1_load(smbase,               a0p,          b0p,          K, tid);
    CP_COMMIT();
    gm1_load(smbase + G1STAGE,     a0p + GK,     b0p + GK,     K, tid);
    CP_COMMIT();
    gm1_load(smbase + 2 * G1STAGE, a0p + 2 * GK, b0p + 2 * GK, K, tid);
    CP_COMMIT();

    for (int s = 0; s < NS; s++) {
        CP_WAIT2();
        __syncthreads();

        const uint32_t sb = smbase + (uint32_t)(s & 3) * G1STAGE;
        uint32_t f0[16], f1[16];
        g1_ldfr(f0, sb, a_off, b_off, 0);

        int t = s + 3;
        if (t < NS)
            gm1_load(smbase + (uint32_t)(t & 3) * G1STAGE,
                     a0p + (size_t)t * GK, b0p + (size_t)t * GK, K, tid);
        CP_COMMIT();

        g1_ldfr(f1, sb, a_off, b_off, 32);
        g1_mma(acc, f0);
        g1_mma(acc, f1);
    }

    const int er = m0 + wr * 32 + (lane >> 2);
    const int ec = n0 + wc * 32 + 2 * (lane & 3);
    #pragma unroll
    for (int i = 0; i < 2; i++)
        #pragma unroll
        for (int j = 0; j < 4; j++) {
            int r = er + i * 16, c = ec + j * 8;
            *(float2*)(C + (size_t)r * N + c) =
                make_float2(acc[i][j][0], acc[i][j][1]);
            *(float2*)(C + (size_t)(r + 8) * N + c) =
                make_float2(acc[i][j][2], acc[i][j][3]);
        }
}

// ---------------------------------------------------------------------------
// HMMA flash attention, fp16 2-term: Q split, K single; P split, V single.
// ctx written single fp16. CTA = 128 q rows x one (b,h); 8 warps.
// ---------------------------------------------------------------------------
#define AROW 144
#define AQ_BYTES (128 * AROW)
#define AKV_BYTES (64 * AROW)
#define AST (2 * AKV_BYTES)
#define ATT_SMEM (2 * AQ_BYTES + 3 * AST)

__device__ __forceinline__ void att_load_kv(
    uint32_t base, const hf* khp, const hf* vhp, int kt, int tid)
{
    #pragma unroll
    for (int i = 0; i < 2; i++) {
        int c = i * 256 + tid;
        int row = c >> 3, col = c & 7;
        uint32_t so = (uint32_t)(row * AROW + col * 16);
        size_t g = (size_t)(kt * 64 + row) * HDIM + col * 8;
        CP16(base + so,             khp + g);
        CP16(base + AKV_BYTES + so, vhp + g);
    }
}

__device__ __forceinline__ void ld_kfr(uint32_t* f, uint32_t kvb, uint32_t kb_off, int ks)
{
    #pragma unroll
    for (int g = 0; g < 4; g++)
        ldsm4(f + g * 4, kvb + kb_off + (uint32_t)(g * 16 * AROW) + (uint32_t)(ks * 32));
}
__device__ __forceinline__ void ld_vfr(uint32_t* f, uint32_t kvb, uint32_t vb_off, int ks)
{
    #pragma unroll
    for (int g = 0; g < 4; g++)
        ldsm4t(f + g * 4, kvb + AKV_BYTES + vb_off
                        + (uint32_t)(ks * 16 * AROW) + (uint32_t)(g * 32));
}

__global__ __launch_bounds__(256) void flash_hmma(
    const hf* __restrict__ qh, const hf* __restrict__ ql,
    const hf* __restrict__ kh, const hf* __restrict__ vh,
    hf* __restrict__ chi)
{
    extern __shared__ __align__(128) char asmbuf[];
    const uint32_t sb = smem_u32(asmbuf);
    const int tid = threadIdx.x, wid = tid >> 5, lane = tid & 31;
    const int qt = 15 - (int)blockIdx.x;
    const int h = blockIdx.y, b = blockIdx.z;
    const int q0 = qt * 128;
    const int ktmax = 2 * qt + 1;

    const size_t headoff = ((size_t)b * NHEAD + h) * SEQ * HDIM;
    const hf* qhp = qh + headoff + (size_t)q0 * HDIM;
    const hf* qlp = ql + headoff + (size_t)q0 * HDIM;
    const hf* khp = kh + headoff;
    const hf* vhp = vh + headoff;

    #pragma unroll
    for (int i = 0; i < 4; i++) {
        int c = i * 256 + tid;
        int row = c >> 3, col = c & 7;
        uint32_t so = (uint32_t)(row * AROW + col * 16);
        size_t g = (size_t)row * HDIM + col * 8;
        CP16(sb + so,            qhp + g);
        CP16(sb + AQ_BYTES + so, qlp + g);
    }
    att_load_kv(sb + 2 * AQ_BYTES, khp, vhp, 0, tid);
    CP_COMMIT();
    att_load_kv(sb + 2 * AQ_BYTES + AST, khp, vhp, 1, tid);
    CP_COMMIT();

    float s[8][4], acc[8][4];
    float m0v = -1e30f, m1v = -1e30f, l0v = 0.f, l1v = 0.f;
    #pragma unroll
    for (int nc = 0; nc < 8; nc++) {
        acc[nc][0] = acc[nc][1] = acc[nc][2] = acc[nc][3] = 0.f;
    }
    uint32_t qfh[16], qfl[16];

    const uint32_t a_off = (uint32_t)((wid * 16 + (lane & 15)) * AROW + (lane >> 4) * 16);
    const uint32_t kb_off = (uint32_t)(((lane >> 4) * 8 + (lane & 7)) * AROW
                                       + (((lane & 15) >> 3) * 16));
    const uint32_t vb_off = (uint32_t)((lane & 15) * AROW + (lane >> 4) * 16);

    for (int kt = 0; kt <= ktmax; kt++) {
        if (kt < ktmax) { CP_WAIT1(); } else { CP_WAIT0(); }
        __syncthreads();

        if (kt == 0) {
            #pragma unroll
            for (int ks = 0; ks < 4; ks++) {
                ldsm4(&qfh[ks * 4], sb + a_off + (uint32_t)(ks * 32));
                ldsm4(&qfl[ks * 4], sb + AQ_BYTES + a_off + (uint32_t)(ks * 32));
            }
        }
        int t = kt + 2;
        if (t <= ktmax) {
            att_load_kv(sb + 2 * AQ_BYTES + (uint32_t)(t % 3) * AST, khp, vhp, t, tid);
            CP_COMMIT();
        }
        const uint32_t kvb = sb + 2 * AQ_BYTES + (uint32_t)(kt % 3) * AST;

        // ---- scores = Q K^T (2-term: qh*K + ql*K) ----
        #pragma unroll
        for (int nc = 0; nc < 8; nc++) {
            s[nc][0] = s[nc][1] = s[nc][2] = s[nc][3] = 0.f;
        }
        {
            uint32_t kfb[2][16];
            ld_kfr(kfb[0], kvb, kb_off, 0);
            #pragma unroll
            for (int ks = 0; ks < 4; ks++) {
                if (ks < 3) ld_kfr(kfb[(ks + 1) & 1], kvb, kb_off, ks + 1);
                const uint32_t* kf = kfb[ks & 1];
                #pragma unroll
                for (int nc = 0; nc < 8; nc++)
                    mma16816(s[nc], &qfh[ks * 4], kf + (nc >> 1) * 4 + (nc & 1) * 2);
                #pragma unroll
                for (int nc = 0; nc < 8; nc++)
                    mma16816(s[nc], &qfl[ks * 4], kf + (nc >> 1) * 4 + (nc & 1) * 2);
            }
        }

        // ---- online softmax (log2 domain; scores pre-scaled by log2e/8) ----
        if (kt >= 2 * qt) {
            const int keyb = kt * 64 + 2 * (lane & 3);
            const int r0 = q0 + wid * 16 + (lane >> 2);
            #pragma unroll
            for (int nc = 0; nc < 8; nc++) {
                int k0 = keyb + nc * 8;
                if (k0     > r0)     s[nc][0] = -1e30f;
                if (k0 + 1 > r0)     s[nc][1] = -1e30f;
                if (k0     > r0 + 8) s[nc][2] = -1e30f;
                if (k0 + 1 > r0 + 8) s[nc][3] = -1e30f;
            }
        }
        float mx0 = -1e30f, mx1 = -1e30f;
        #pragma unroll
        for (int nc = 0; nc < 8; nc++) {
            mx0 = fmaxf(mx0, fmaxf(s[nc][0], s[nc][1]));
            mx1 = fmaxf(mx1, fmaxf(s[nc][2], s[nc][3]));
        }
        mx0 = fmaxf(mx0, __shfl_xor_sync(0xffffffffu, mx0, 1));
        mx0 = fmaxf(mx0, __shfl_xor_sync(0xffffffffu, mx0, 2));
        mx1 = fmaxf(mx1, __shfl_xor_sync(0xffffffffu, mx1, 1));
        mx1 = fmaxf(mx1, __shfl_xor_sync(0xffffffffu, mx1, 2));
        float mn0 = fmaxf(m0v, mx0), mn1 = fmaxf(m1v, mx1);
        float c0 = ex2(m0v - mn0), c1 = ex2(m1v - mn1);
        float su0 = 0.f, su1 = 0.f;
        #pragma unroll
        for (int nc = 0; nc < 8; nc++) {
            s[nc][0] = ex2(s[nc][0] - mn0);
            s[nc][1] = ex2(s[nc][1] - mn0);
            s[nc][2] = ex2(s[nc][2] - mn1);
            s[nc][3] = ex2(s[nc][3] - mn1);
            su0 += s[nc][0] + s[nc][1];
            su1 += s[nc][2] + s[nc][3];
        }
        su0 += __shfl_xor_sync(0xffffffffu, su0, 1);
        su0 += __shfl_xor_sync(0xffffffffu, su0, 2);
        su1 += __shfl_xor_sync(0xffffffffu, su1, 1);
        su1 += __shfl_xor_sync(0xffffffffu, su1, 2);
        l0v = l0v * c0 + su0;
        l1v = l1v * c1 + su1;
        m0v = mn0; m1v = mn1;
        #pragma unroll
        for (int nc = 0; nc < 8; nc++) {
            acc[nc][0] *= c0; acc[nc][1] *= c0;
            acc[nc][2] *= c1; acc[nc][3] *= c1;
        }

        // ---- ctx += P V (2-term: ph*V + pl*V) ----
        {
            uint32_t vfb[2][16];
            ld_vfr(vfb[0], kvb, vb_off, 0);
            #pragma unroll
            for (int ks = 0; ks < 4; ks++) {
                if (ks < 3) ld_vfr(vfb[(ks + 1) & 1], kvb, vb_off, ks + 1);
                uint32_t ph[4], pl[4];
                split2(s[2 * ks][0],     s[2 * ks][1],     ph[0], pl[0]);
                split2(s[2 * ks][2],     s[2 * ks][3],     ph[1], pl[1]);
                split2(s[2 * ks + 1][0], s[2 * ks + 1][1], ph[2], pl[2]);
                split2(s[2 * ks + 1][2], s[2 * ks + 1][3], ph[3], pl[3]);
                const uint32_t* vf = vfb[ks & 1];
                #pragma unroll
                for (int nc = 0; nc < 8; nc++)
                    mma16816(acc[nc], ph, vf + (nc >> 1) * 4 + (nc & 1) * 2);
                #pragma unroll
                for (int nc = 0; nc < 8; nc++)
                    mma16816(acc[nc], pl, vf + (nc >> 1) * 4 + (nc & 1) * 2);
            }
        }
    }

    float i0 = 1.f / l0v, i1 = 1.f / l1v;
    const int r0 = q0 + wid * 16 + (lane >> 2);
    const int cb = h * HDIM + 2 * (lane & 3);
    #pragma unroll
    for (int nc = 0; nc < 8; nc++) {
        int cc = cb + nc * 8;
        size_t off = (size_t)(b * SEQ + r0) * DMODEL + cc;
        *(uint32_t*)(chi + off) = packhf(acc[nc][0] * i0, acc[nc][1] * i0);
        off = (size_t)(b * SEQ + r0 + 8) * DMODEL + cc;
        *(uint32_t*)(chi + off) = packhf(acc[nc][2] * i1, acc[nc][3] * i1);
    }
}

// ---------------------------------------------------------------------------
extern "C" void kernel_launch(void* const* d_in, const int* in_sizes, int n_in,
                              void* d_out, int out_size)
{
    (void)in_sizes; (void)n_in; (void)out_size;
    const float* x     = (const float*)d_in[0];
    const float* W_qkv = (const float*)d_in[1];
    const float* b_qkv = (const float*)d_in[2];
    const float* W_out = (const float*)d_in[3];
    float* out = (float*)d_out;

    hf *xhi, *xlo, *wqh, *woh, *chi;
    hf *qh, *ql, *kh, *vh;
    cudaGetSymbolAddress((void**)&xhi, g_xhi);
    cudaGetSymbolAddress((void**)&xlo, g_xlo);
    cudaGetSymbolAddress((void**)&wqh, g_wqh);
    cudaGetSymbolAddress((void**)&woh, g_woh);
    cudaGetSymbolAddress((void**)&chi, g_chi);
    cudaGetSymbolAddress((void**)&qh, g_qh);
    cudaGetSymbolAddress((void**)&ql, g_ql);
    cudaGetSymbolAddress((void**)&kh, g_kh);
    cudaGetSymbolAddress((void**)&vh, g_vh);

    cudaFuncSetAttribute(gemm_qkv, cudaFuncAttributeMaxDynamicSharedMemorySize, G2_DYN);
    cudaFuncSetAttribute(gemm_out, cudaFuncAttributeMaxDynamicSharedMemorySize, G1_DYN);
    cudaFuncSetAttribute(flash_hmma, cudaFuncAttributeMaxDynamicSharedMemorySize, ATT_SMEM);

    // fused pre-pass (one launch)
    prep_kernel<<<8192, 256>>>(x, W_qkv, W_out, xhi, xlo, wqh, woh);

    gemm_qkv<<<dim3(QKV_N / 128, ROWS / 128), 512, G2_DYN>>>(
        xhi, xlo, wqh, b_qkv, qh, ql, kh, vh, ROWS, QKV_N, DMODEL);

    flash_hmma<<<dim3(16, NHEAD, BATCH), 256, ATT_SMEM>>>(
        qh, ql, kh, vh, chi);

    gemm_out<<<dim3(DMODEL / 128, ROWS / 128), 512, G1_DYN>>>(
        chi, woh, out, ROWS, DMODEL, DMODEL);
}

// round 16
// speedup vs baseline: 2.0400x; 1.2625x over previous
#include <cuda_runtime.h>
#include <cuda_fp16.h>
#include <math.h>
#include <stdint.h>

#define BATCH 2
#define SEQ   2048
#define DMODEL 1024
#define NHEAD 16
#define HDIM  64
#define ROWS  (BATCH*SEQ)          // 4096
#define QKV_N (3*DMODEL)           // 3072

typedef __half hf;

// ---------------------------------------------------------------------------
// Device scratch (fp16, all single precision representations)
// ---------------------------------------------------------------------------
__device__ hf g_xh[(size_t)ROWS * DMODEL];
__device__ hf g_wqh[(size_t)QKV_N * DMODEL];   // W_qkv^T single fp16
__device__ hf g_woh[(size_t)DMODEL * DMODEL];  // W_out^T single fp16
__device__ hf g_chi[(size_t)ROWS * DMODEL];    // ctx single fp16
// q (pre-scaled), k, v single fp16. layout [b][h][s][d]
__device__ hf g_qh[(size_t)BATCH * NHEAD * SEQ * HDIM];
__device__ hf g_kh[(size_t)BATCH * NHEAD * SEQ * HDIM];
__device__ hf g_vh[(size_t)BATCH * NHEAD * SEQ * HDIM];

// ---------------------------------------------------------------------------
// PTX helpers
// ---------------------------------------------------------------------------
__device__ __forceinline__ uint32_t smem_u32(const void* p) {
    uint32_t a;
    asm("{ .reg .u64 t; cvta.to.shared.u64 t, %1; cvt.u32.u64 %0, t; }" : "=r"(a) : "l"(p));
    return a;
}
#define CP16(sm, gm) asm volatile("cp.async.cg.shared.global [%0], [%1], 16;" :: "r"(sm), "l"(gm))
#define CP_COMMIT()  asm volatile("cp.async.commit_group;" ::: "memory")
#define CP_WAIT2()   asm volatile("cp.async.wait_group 2;" ::: "memory")
#define CP_WAIT1()   asm volatile("cp.async.wait_group 1;" ::: "memory")
#define CP_WAIT0()   asm volatile("cp.async.wait_group 0;" ::: "memory")

__device__ __forceinline__ void ldsm4(uint32_t* r, uint32_t addr) {
    asm volatile("ldmatrix.sync.aligned.m8n8.x4.shared.b16 {%0,%1,%2,%3}, [%4];"
                 : "=r"(r[0]), "=r"(r[1]), "=r"(r[2]), "=r"(r[3]) : "r"(addr));
}
__device__ __forceinline__ void ldsm4t(uint32_t* r, uint32_t addr) {
    asm volatile("ldmatrix.sync.aligned.m8n8.x4.trans.shared.b16 {%0,%1,%2,%3}, [%4];"
                 : "=r"(r[0]), "=r"(r[1]), "=r"(r[2]), "=r"(r[3]) : "r"(addr));
}
__device__ __forceinline__ void mma16816(float* c, const uint32_t* a, const uint32_t* b) {
    asm volatile(
        "mma.sync.aligned.m16n8k16.row.col.f32.f16.f16.f32 "
        "{%0,%1,%2,%3}, {%4,%5,%6,%7}, {%8,%9}, {%0,%1,%2,%3};"
        : "+f"(c[0]), "+f"(c[1]), "+f"(c[2]), "+f"(c[3])
        : "r"(a[0]), "r"(a[1]), "r"(a[2]), "r"(a[3]), "r"(b[0]), "r"(b[1]));
}
__device__ __forceinline__ float ex2(float x) {
    float y;
    asm("ex2.approx.f32 %0, %1;" : "=f"(y) : "f"(x));
    return y;
}
__device__ __forceinline__ uint32_t packhf(float x, float y) {
    __half2 t = __floats2half2_rn(x, y);   // x -> low half
    return *(uint32_t*)&t;
}
__device__ __forceinline__ void split2(float x, float y, uint32_t& h, uint32_t& l) {
    h = packhf(x, y);
    __half2 hh = *(__half2*)&h;
    l = packhf(x - __half2float(__low2half(hh)), y - __half2float(__high2half(hh)));
}

// ---------------------------------------------------------------------------
// Fused pre-pass: x -> fp16; W_qkv^T, W_out^T -> fp16 (transposed).
// ---------------------------------------------------------------------------
__global__ __launch_bounds__(256) void prep_kernel(
    const float* __restrict__ x, const float* __restrict__ Wq,
    const float* __restrict__ Wo,
    hf* __restrict__ xh, hf* __restrict__ wqh, hf* __restrict__ woh)
{
    __shared__ float t[32][33];
    const int blk = blockIdx.x, tid = threadIdx.x;

    if (blk < 4096) {
        int i = blk * 256 + tid;
        float4 v = ((const float4*)x)[i];
        *(uint2*)(xh + 4 * (size_t)i) =
            make_uint2(packhf(v.x, v.y), packhf(v.z, v.w));
        return;
    }

    const float* W; hf* hi;
    int K, N, bx, by;
    if (blk < 7168) {
        int idx = blk - 4096;
        W = Wq; hi = wqh; K = DMODEL; N = QKV_N;
        bx = idx % 96; by = idx / 96;
    } else {
        int idx = blk - 7168;
        W = Wo; hi = woh; K = DMODEL; N = DMODEL;
        bx = idx & 31; by = idx >> 5;
    }
    const int tx = tid & 31, ty = tid >> 5;
    const int n0 = bx * 32, k0 = by * 32;
    #pragma unroll
    for (int i = 0; i < 4; i++)
        t[ty + i * 8][tx] = W[(size_t)(k0 + ty + i * 8) * N + n0 + tx];
    __syncthreads();
    #pragma unroll
    for (int i = 0; i < 4; i++) {
        float v = t[tx][ty + i * 8];
        size_t o = (size_t)(n0 + ty + i * 8) * K + k0 + tx;
        hi[o] = __float2half_rn(v);
    }
}

// ---------------------------------------------------------------------------
// GEMM geometry (R11 proven): 512 thr, 16 warps (4x4), warp 32x32,
// CTA 128x128, BK=32, 4-stage cp.async ring, wait2, 1-term fp16 MMAs.
// ---------------------------------------------------------------------------
#define GK 32
#define GROW 80
#define GSUB (128 * GROW)
#define G1STAGE (2 * GSUB)     // A|B = 20480
#define G1_DYN (4 * G1STAGE + 256)

__device__ __forceinline__ void gm1_load(
    uint32_t buf, const hf* ga, const hf* gb, int K, int tid)
{
    int row = tid >> 2, col = tid & 3;
    uint32_t so = (uint32_t)(row * GROW + col * 16);
    size_t g = (size_t)row * K + (size_t)col * 8;
    CP16(buf + so,        ga + g);
    CP16(buf + GSUB + so, gb + g);
}

__device__ __forceinline__ void g1_ldfr(uint32_t* fr, uint32_t sb,
                                        uint32_t a_off, uint32_t b_off, uint32_t ko)
{
    ldsm4(fr + 0,  sb + a_off + ko);
    ldsm4(fr + 4,  sb + a_off + 16u * GROW + ko);
    ldsm4(fr + 8,  sb + GSUB + b_off + ko);
    ldsm4(fr + 12, sb + GSUB + b_off + 16u * GROW + ko);
}

__device__ __forceinline__ void g1_mma(float acc[2][4][4], const uint32_t* fr)
{
    const uint32_t* a = fr;
    const uint32_t* b = fr + 8;
    #pragma unroll
    for (int i = 0; i < 2; i++)
        #pragma unroll
        for (int j = 0; j < 4; j++)
            mma16816(acc[i][j], a + i * 4, b + (j >> 1) * 4 + (j & 1) * 2);
}

// QKV GEMM: 1-term, fused scatter epilogue (q scaled, all outputs fp16).
__global__ __launch_bounds__(512, 1) void gemm_qkv(
    const hf* __restrict__ A, const hf* __restrict__ B,
    const float* __restrict__ bias,
    hf* __restrict__ oqh, hf* __restrict__ okh, hf* __restrict__ ovh,
    int M, int N, int K)
{
    extern __shared__ __align__(128) char dynsm[];
    const uint32_t smbase = smem_u32(dynsm);

    const int tid = threadIdx.x;
    const int wid = tid >> 5, lane = tid & 31;
    const int wr = wid >> 2, wc = wid & 3;
    const int m0 = blockIdx.y * 128, n0 = blockIdx.x * 128;

    const hf* a0p = A + (size_t)m0 * K;
    const hf* b0p = B + (size_t)n0 * K;

    const uint32_t a_off = (uint32_t)((wr * 32 + (lane & 15)) * GROW + (lane >> 4) * 16);
    const uint32_t b_off = (uint32_t)((wc * 32 + (lane >> 4) * 8 + (lane & 7)) * GROW
                                      + (((lane & 15) >> 3) * 16));

    float acc[2][4][4];
    #pragma unroll
    for (int i = 0; i < 2; i++)
        #pragma unroll
        for (int j = 0; j < 4; j++)
            #pragma unroll
            for (int r = 0; r < 4; r++) acc[i][j][r] = 0.f;

    const int NS = K / GK;

    gm1_load(smbase,               a0p,          b0p,          K, tid);
    CP_COMMIT();
    gm1_load(smbase + G1STAGE,     a0p + GK,     b0p + GK,     K, tid);
    CP_COMMIT();
    gm1_load(smbase + 2 * G1STAGE, a0p + 2 * GK, b0p + 2 * GK, K, tid);
    CP_COMMIT();

    for (int s = 0; s < NS; s++) {
        CP_WAIT2();
        __syncthreads();

        const uint32_t sb = smbase + (uint32_t)(s & 3) * G1STAGE;
        uint32_t f0[16], f1[16];
        g1_ldfr(f0, sb, a_off, b_off, 0);

        int t = s + 3;
        if (t < NS)
            gm1_load(smbase + (uint32_t)(t & 3) * G1STAGE,
                     a0p + (size_t)t * GK, b0p + (size_t)t * GK, K, tid);
        CP_COMMIT();

        g1_ldfr(f1, sb, a_off, b_off, 32);
        g1_mma(acc, f0);
        g1_mma(acc, f1);
    }

    const int er = m0 + wr * 32 + (lane >> 2);
    const int ec = n0 + wc * 32 + 2 * (lane & 3);
    const int part = ec >> 10;
    // q scale folded in LOG2 domain: 1/sqrt(64) * log2(e)
    const float sc = (part == 0) ? 0.18033688f : 1.0f;
    hf* dst = (part == 0) ? oqh : ((part == 1) ? okh : ovh);
    #pragma unroll
    for (int i = 0; i < 2; i++)
        #pragma unroll
        for (int j = 0; j < 4; j++) {
            int r = er + i * 16, c = ec + j * 8;
            int hh = (c >> 6) & 15, d = c & 63;
            float b0 = bias[c], b1 = bias[c + 1];
            size_t off  = (((size_t)(r >> 11) * NHEAD + hh) * SEQ + (r & 2047)) * HDIM + d;
            int r2 = r + 8;
            size_t off2 = (((size_t)(r2 >> 11) * NHEAD + hh) * SEQ + (r2 & 2047)) * HDIM + d;
            *(uint32_t*)(dst + off)  = packhf((acc[i][j][0] + b0) * sc, (acc[i][j][1] + b1) * sc);
            *(uint32_t*)(dst + off2) = packhf((acc[i][j][2] + b0) * sc, (acc[i][j][3] + b1) * sc);
        }
}

// out-proj GEMM: 1-term, fp32 C.
__global__ __launch_bounds__(512, 1) void gemm_out(
    const hf* __restrict__ A, const hf* __restrict__ B, float* __restrict__ C,
    int M, int N, int K)
{
    extern __shared__ __align__(128) char dynsm[];
    const uint32_t smbase = smem_u32(dynsm);

    const int tid = threadIdx.x;
    const int wid = tid >> 5, lane = tid & 31;
    const int wr = wid >> 2, wc = wid & 3;
    const int m0 = blockIdx.y * 128, n0 = blockIdx.x * 128;

    const hf* a0p = A + (size_t)m0 * K;
    const hf* b0p = B + (size_t)n0 * K;

    const uint32_t a_off = (uint32_t)((wr * 32 + (lane & 15)) * GROW + (lane >> 4) * 16);
    const uint32_t b_off = (uint32_t)((wc * 32 + (lane >> 4) * 8 + (lane & 7)) * GROW
                                      + (((lane & 15) >> 3) * 16));

    float acc[2][4][4];
    #pragma unroll
    for (int i = 0; i < 2; i++)
        #pragma unroll
        for (int j = 0; j < 4; j++)
            #pragma unroll
            for (int r = 0; r < 4; r++) acc[i][j][r] = 0.f;

    const int NS = K / GK;

    gm1_load(smbase,               a0p,          b0p,          K, tid);
    CP_COMMIT();
    gm1_load(smbase + G1STAGE,     a0p + GK,     b0p + GK,     K, tid);
    CP_COMMIT();
    gm1_load(smbase + 2 * G1STAGE, a0p + 2 * GK, b0p + 2 * GK, K, tid);
    CP_COMMIT();

    for (int s = 0; s < NS; s++) {
        CP_WAIT2();
        __syncthreads();

        const uint32_t sb = smbase + (uint32_t)(s & 3) * G1STAGE;
        uint32_t f0[16], f1[16];
        g1_ldfr(f0, sb, a_off, b_off, 0);

        int t = s + 3;
        if (t < NS)
            gm1_load(smbase + (uint32_t)(t & 3) * G1STAGE,
                     a0p + (size_t)t * GK, b0p + (size_t)t * GK, K, tid);
        CP_COMMIT();

        g1_ldfr(f1, sb, a_off, b_off, 32);
        g1_mma(acc, f0);
        g1_mma(acc, f1);
    }

    const int er = m0 + wr * 32 + (lane >> 2);
    const int ec = n0 + wc * 32 + 2 * (lane & 3);
    #pragma unroll
    for (int i = 0; i < 2; i++)
        #pragma unroll
        for (int j = 0; j < 4; j++) {
            int r = er + i * 16, c = ec + j * 8;
            *(float2*)(C + (size_t)r * N + c) =
                make_float2(acc[i][j][0], acc[i][j][1]);
            *(float2*)(C + (size_t)(r + 8) * N + c) =
                make_float2(acc[i][j][2], acc[i][j][3]);
        }
}

// ---------------------------------------------------------------------------
// HMMA flash attention: Q single fp16 (pre-scaled), K single; P split, V single.
// ctx written single fp16. CTA = 128 q rows x one (b,h); 8 warps.
// ---------------------------------------------------------------------------
#define AROW 144
#define AQ_BYTES (128 * AROW)
#define AKV_BYTES (64 * AROW)
#define AST (2 * AKV_BYTES)
#define ATT_SMEM (AQ_BYTES + 3 * AST)   // 18432 + 55296 = 73728

__device__ __forceinline__ void att_load_kv(
    uint32_t base, const hf* khp, const hf* vhp, int kt, int tid)
{
    #pragma unroll
    for (int i = 0; i < 2; i++) {
        int c = i * 256 + tid;
        int row = c >> 3, col = c & 7;
        uint32_t so = (uint32_t)(row * AROW + col * 16);
        size_t g = (size_t)(kt * 64 + row) * HDIM + col * 8;
        CP16(base + so,             khp + g);
        CP16(base + AKV_BYTES + so, vhp + g);
    }
}

__device__ __forceinline__ void ld_kfr(uint32_t* f, uint32_t kvb, uint32_t kb_off, int ks)
{
    #pragma unroll
    for (int g = 0; g < 4; g++)
        ldsm4(f + g * 4, kvb + kb_off + (uint32_t)(g * 16 * AROW) + (uint32_t)(ks * 32));
}
__device__ __forceinline__ void ld_vfr(uint32_t* f, uint32_t kvb, uint32_t vb_off, int ks)
{
    #pragma unroll
    for (int g = 0; g < 4; g++)
        ldsm4t(f + g * 4, kvb + AKV_BYTES + vb_off
                        + (uint32_t)(ks * 16 * AROW) + (uint32_t)(g * 32));
}

__global__ __launch_bounds__(256) void flash_hmma(
    const hf* __restrict__ qh, const hf* __restrict__ kh,
    const hf* __restrict__ vh, hf* __restrict__ chi)
{
    extern __shared__ __align__(128) char asmbuf[];
    const uint32_t sb = smem_u32(asmbuf);
    const int tid = threadIdx.x, wid = tid >> 5, lane = tid & 31;
    const int qt = 15 - (int)blockIdx.x;
    const int h = blockIdx.y, b = blockIdx.z;
    const int q0 = qt * 128;
    const int ktmax = 2 * qt + 1;

    const size_t headoff = ((size_t)b * NHEAD + h) * SEQ * HDIM;
    const hf* qhp = qh + headoff + (size_t)q0 * HDIM;
    const hf* khp = kh + headoff;
    const hf* vhp = vh + headoff;

    #pragma unroll
    for (int i = 0; i < 4; i++) {
        int c = i * 256 + tid;
        int row = c >> 3, col = c & 7;
        uint32_t so = (uint32_t)(row * AROW + col * 16);
        size_t g = (size_t)row * HDIM + col * 8;
        CP16(sb + so, qhp + g);
    }
    att_load_kv(sb + AQ_BYTES, khp, vhp, 0, tid);
    CP_COMMIT();
    att_load_kv(sb + AQ_BYTES + AST, khp, vhp, 1, tid);
    CP_COMMIT();

    float s[8][4], acc[8][4];
    float m0v = -1e30f, m1v = -1e30f, l0v = 0.f, l1v = 0.f;
    #pragma unroll
    for (int nc = 0; nc < 8; nc++) {
        acc[nc][0] = acc[nc][1] = acc[nc][2] = acc[nc][3] = 0.f;
    }
    uint32_t qf[16];

    const uint32_t a_off = (uint32_t)((wid * 16 + (lane & 15)) * AROW + (lane >> 4) * 16);
    const uint32_t kb_off = (uint32_t)(((lane >> 4) * 8 + (lane & 7)) * AROW
                                       + (((lane & 15) >> 3) * 16));
    const uint32_t vb_off = (uint32_t)((lane & 15) * AROW + (lane >> 4) * 16);

    for (int kt = 0; kt <= ktmax; kt++) {
        if (kt < ktmax) { CP_WAIT1(); } else { CP_WAIT0(); }
        __syncthreads();

        if (kt == 0) {
            #pragma unroll
            for (int ks = 0; ks < 4; ks++)
                ldsm4(&qf[ks * 4], sb + a_off + (uint32_t)(ks * 32));
        }
        int t = kt + 2;
        if (t <= ktmax) {
            att_load_kv(sb + AQ_BYTES + (uint32_t)(t % 3) * AST, khp, vhp, t, tid);
            CP_COMMIT();
        }
        const uint32_t kvb = sb + AQ_BYTES + (uint32_t)(kt % 3) * AST;

        // ---- scores = Q K^T (1-term) ----
        #pragma unroll
        for (int nc = 0; nc < 8; nc++) {
            s[nc][0] = s[nc][1] = s[nc][2] = s[nc][3] = 0.f;
        }
        {
            uint32_t kfb[2][16];
            ld_kfr(kfb[0], kvb, kb_off, 0);
            #pragma unroll
            for (int ks = 0; ks < 4; ks++) {
                if (ks < 3) ld_kfr(kfb[(ks + 1) & 1], kvb, kb_off, ks + 1);
                const uint32_t* kf = kfb[ks & 1];
                #pragma unroll
                for (int nc = 0; nc < 8; nc++)
                    mma16816(s[nc], &qf[ks * 4], kf + (nc >> 1) * 4 + (nc & 1) * 2);
            }
        }

        // ---- online softmax (log2 domain; q pre-scaled by log2e/8) ----
        if (kt >= 2 * qt) {
            const int keyb = kt * 64 + 2 * (lane & 3);
            const int r0 = q0 + wid * 16 + (lane >> 2);
            #pragma unroll
            for (int nc = 0; nc < 8; nc++) {
                int k0 = keyb + nc * 8;
                if (k0     > r0)     s[nc][0] = -1e30f;
                if (k0 + 1 > r0)     s[nc][1] = -1e30f;
                if (k0     > r0 + 8) s[nc][2] = -1e30f;
                if (k0 + 1 > r0 + 8) s[nc][3] = -1e30f;
            }
        }
        float mx0 = -1e30f, mx1 = -1e30f;
        #pragma unroll
        for (int nc = 0; nc < 8; nc++) {
            mx0 = fmaxf(mx0, fmaxf(s[nc][0], s[nc][1]));
            mx1 = fmaxf(mx1, fmaxf(s[nc][2], s[nc][3]));
        }
        mx0 = fmaxf(mx0, __shfl_xor_sync(0xffffffffu, mx0, 1));
        mx0 = fmaxf(mx0, __shfl_xor_sync(0xffffffffu, mx0, 2));
        mx1 = fmaxf(mx1, __shfl_xor_sync(0xffffffffu, mx1, 1));
        mx1 = fmaxf(mx1, __shfl_xor_sync(0xffffffffu, mx1, 2));
        float mn0 = fmaxf(m0v, mx0), mn1 = fmaxf(m1v, mx1);
        float c0 = ex2(m0v - mn0), c1 = ex2(m1v - mn1);
        float su0 = 0.f, su1 = 0.f;
        #pragma unroll
        for (int nc = 0; nc < 8; nc++) {
            s[nc][0] = ex2(s[nc][0] - mn0);
            s[nc][1] = ex2(s[nc][1] - mn0);
            s[nc][2] = ex2(s[nc][2] - mn1);
            s[nc][3] = ex2(s[nc][3] - mn1);
            su0 += s[nc][0] + s[nc][1];
            su1 += s[nc][2] + s[nc][3];
        }
        su0 += __shfl_xor_sync(0xffffffffu, su0, 1);
        su0 += __shfl_xor_sync(0xffffffffu, su0, 2);
        su1 += __shfl_xor_sync(0xffffffffu, su1, 1);
        su1 += __shfl_xor_sync(0xffffffffu, su1, 2);
        l0v = l0v * c0 + su0;
        l1v = l1v * c1 + su1;
        m0v = mn0; m1v = mn1;
        #pragma unroll
        for (int nc = 0; nc < 8; nc++) {
            acc[nc][0] *= c0; acc[nc][1] *= c0;
            acc[nc][2] *= c1; acc[nc][3] *= c1;
        }

        // ---- ctx += P V (2-term: ph*V + pl*V) ----
        {
            uint32_t vfb[2][16];
            ld_vfr(vfb[0], kvb, vb_off, 0);
            #pragma unroll
            for (int ks = 0; ks < 4; ks++) {
                if (ks < 3) ld_vfr(vfb[(ks + 1) & 1], kvb, vb_off, ks + 1);
                uint32_t ph[4], pl[4];
                split2(s[2 * ks][0],     s[2 * ks][1],     ph[0], pl[0]);
                split2(s[2 * ks][2],     s[2 * ks][3],     ph[1], pl[1]);
                split2(s[2 * ks + 1][0], s[2 * ks + 1][1], ph[2], pl[2]);
                split2(s[2 * ks + 1][2], s[2 * ks + 1][3], ph[3], pl[3]);
                const uint32_t* vf = vfb[ks & 1];
                #pragma unroll
                for (int nc = 0; nc < 8; nc++)
                    mma16816(acc[nc], ph, vf + (nc >> 1) * 4 + (nc & 1) * 2);
                #pragma unroll
                for (int nc = 0; nc < 8; nc++)
                    mma16816(acc[nc], pl, vf + (nc >> 1) * 4 + (nc & 1) * 2);
            }
        }
    }

    float i0 = 1.f / l0v, i1 = 1.f / l1v;
    const int r0 = q0 + wid * 16 + (lane >> 2);
    const int cb = h * HDIM + 2 * (lane & 3);
    #pragma unroll
    for (int nc = 0; nc < 8; nc++) {
        int cc = cb + nc * 8;
        size_t off = (size_t)(b * SEQ + r0) * DMODEL + cc;
        *(uint32_t*)(chi + off) = packhf(acc[nc][0] * i0, acc[nc][1] * i0);
        off = (size_t)(b * SEQ + r0 + 8) * DMODEL + cc;
        *(uint32_t*)(chi + off) = packhf(acc[nc][2] * i1, acc[nc][3] * i1);
    }
}

// ---------------------------------------------------------------------------
extern "C" void kernel_launch(void* const* d_in, const int* in_sizes, int n_in,
                              void* d_out, int out_size)
{
    (void)in_sizes; (void)n_in; (void)out_size;
    const float* x     = (const float*)d_in[0];
    const float* W_qkv = (const float*)d_in[1];
    const float* b_qkv = (const float*)d_in[2];
    const float* W_out = (const float*)d_in[3];
    float* out = (float*)d_out;

    hf *xh, *wqh, *woh, *chi, *qh, *kh, *vh;
    cudaGetSymbolAddress((void**)&xh, g_xh);
    cudaGetSymbolAddress((void**)&wqh, g_wqh);
    cudaGetSymbolAddress((void**)&woh, g_woh);
    cudaGetSymbolAddress((void**)&chi, g_chi);
    cudaGetSymbolAddress((void**)&qh, g_qh);
    cudaGetSymbolAddress((void**)&kh, g_kh);
    cudaGetSymbolAddress((void**)&vh, g_vh);

    cudaFuncSetAttribute(gemm_qkv, cudaFuncAttributeMaxDynamicSharedMemorySize, G1_DYN);
    cudaFuncSetAttribute(gemm_out, cudaFuncAttributeMaxDynamicSharedMemorySize, G1_DYN);
    cudaFuncSetAttribute(flash_hmma, cudaFuncAttributeMaxDynamicSharedMemorySize, ATT_SMEM);

    // fused pre-pass (one launch)
    prep_kernel<<<8192, 256>>>(x, W_qkv, W_out, xh, wqh, woh);

    gemm_qkv<<<dim3(QKV_N / 128, ROWS / 128), 512, G1_DYN>>>(
        xh, wqh, b_qkv, qh, kh, vh, ROWS, QKV_N, DMODEL);

    flash_hmma<<<dim3(16, NHEAD, BATCH), 256, ATT_SMEM>>>(
        qh, kh, vh, chi);

    gemm_out<<<dim3(DMODEL / 128, ROWS / 128), 512, G1_DYN>>>(
        chi, woh, out, ROWS, DMODEL, DMODEL);
}

// round 17
// speedup vs baseline: 2.1876x; 1.0724x over previous
#include <cuda_runtime.h>
#include <cuda_fp16.h>
#include <math.h>
#include <stdint.h>

#define BATCH 2
#define SEQ   2048
#define DMODEL 1024
#define NHEAD 16
#define HDIM  64
#define ROWS  (BATCH*SEQ)          // 4096
#define QKV_N (3*DMODEL)           // 3072

typedef __half hf;

// ---------------------------------------------------------------------------
// Device scratch (fp16)
// ---------------------------------------------------------------------------
__device__ hf g_xh[(size_t)ROWS * DMODEL];
__device__ hf g_wqh[(size_t)QKV_N * DMODEL];   // W_qkv^T fp16
__device__ hf g_woh[(size_t)DMODEL * DMODEL];  // W_out^T fp16
__device__ hf g_chi[(size_t)ROWS * DMODEL];    // ctx fp16
// q (pre-scaled), k, v fp16. layout [b][h][s][d]
__device__ hf g_qh[(size_t)BATCH * NHEAD * SEQ * HDIM];
__device__ hf g_kh[(size_t)BATCH * NHEAD * SEQ * HDIM];
__device__ hf g_vh[(size_t)BATCH * NHEAD * SEQ * HDIM];

// ---------------------------------------------------------------------------
// PTX helpers
// ---------------------------------------------------------------------------
__device__ __forceinline__ uint32_t smem_u32(const void* p) {
    uint32_t a;
    asm("{ .reg .u64 t; cvta.to.shared.u64 t, %1; cvt.u32.u64 %0, t; }" : "=r"(a) : "l"(p));
    return a;
}
#define CP16(sm, gm) asm volatile("cp.async.cg.shared.global [%0], [%1], 16;" :: "r"(sm), "l"(gm))
#define CP_COMMIT()  asm volatile("cp.async.commit_group;" ::: "memory")
#define CP_WAIT4()   asm volatile("cp.async.wait_group 4;" ::: "memory")
#define CP_WAIT1()   asm volatile("cp.async.wait_group 1;" ::: "memory")
#define CP_WAIT0()   asm volatile("cp.async.wait_group 0;" ::: "memory")

__device__ __forceinline__ void ldsm4(uint32_t* r, uint32_t addr) {
    asm volatile("ldmatrix.sync.aligned.m8n8.x4.shared.b16 {%0,%1,%2,%3}, [%4];"
                 : "=r"(r[0]), "=r"(r[1]), "=r"(r[2]), "=r"(r[3]) : "r"(addr));
}
__device__ __forceinline__ void ldsm4t(uint32_t* r, uint32_t addr) {
    asm volatile("ldmatrix.sync.aligned.m8n8.x4.trans.shared.b16 {%0,%1,%2,%3}, [%4];"
                 : "=r"(r[0]), "=r"(r[1]), "=r"(r[2]), "=r"(r[3]) : "r"(addr));
}
__device__ __forceinline__ void mma16816(float* c, const uint32_t* a, const uint32_t* b) {
    asm volatile(
        "mma.sync.aligned.m16n8k16.row.col.f32.f16.f16.f32 "
        "{%0,%1,%2,%3}, {%4,%5,%6,%7}, {%8,%9}, {%0,%1,%2,%3};"
        : "+f"(c[0]), "+f"(c[1]), "+f"(c[2]), "+f"(c[3])
        : "r"(a[0]), "r"(a[1]), "r"(a[2]), "r"(a[3]), "r"(b[0]), "r"(b[1]));
}
__device__ __forceinline__ float ex2(float x) {
    float y;
    asm("ex2.approx.f32 %0, %1;" : "=f"(y) : "f"(x));
    return y;
}
__device__ __forceinline__ uint32_t packhf(float x, float y) {
    __half2 t = __floats2half2_rn(x, y);   // x -> low half
    return *(uint32_t*)&t;
}

// ---------------------------------------------------------------------------
// Fused pre-pass: x -> fp16; W_qkv^T, W_out^T -> fp16 (transposed).
// ---------------------------------------------------------------------------
__global__ __launch_bounds__(256) void prep_kernel(
    const float* __restrict__ x, const float* __restrict__ Wq,
    const float* __restrict__ Wo,
    hf* __restrict__ xh, hf* __restrict__ wqh, hf* __restrict__ woh)
{
    __shared__ float t[32][33];
    const int blk = blockIdx.x, tid = threadIdx.x;

    if (blk < 4096) {
        int i = blk * 256 + tid;
        float4 v = ((const float4*)x)[i];
        *(uint2*)(xh + 4 * (size_t)i) =
            make_uint2(packhf(v.x, v.y), packhf(v.z, v.w));
        return;
    }

    const float* W; hf* hi;
    int K, N, bx, by;
    if (blk < 7168) {
        int idx = blk - 4096;
        W = Wq; hi = wqh; K = DMODEL; N = QKV_N;
        bx = idx % 96; by = idx / 96;
    } else {
        int idx = blk - 7168;
        W = Wo; hi = woh; K = DMODEL; N = DMODEL;
        bx = idx & 31; by = idx >> 5;
    }
    const int tx = tid & 31, ty = tid >> 5;
    const int n0 = bx * 32, k0 = by * 32;
    #pragma unroll
    for (int i = 0; i < 4; i++)
        t[ty + i * 8][tx] = W[(size_t)(k0 + ty + i * 8) * N + n0 + tx];
    __syncthreads();
    #pragma unroll
    for (int i = 0; i < 4; i++) {
        float v = t[tx][ty + i * 8];
        size_t o = (size_t)(n0 + ty + i * 8) * K + k0 + tx;
        hi[o] = __float2half_rn(v);
    }
}

// ---------------------------------------------------------------------------
// GEMM geometry: 512 thr, 16 warps (4x4), warp 32x32, CTA 128x128, BK=32.
// R17: 6-stage cp.async ring, wait4 (deeper pipeline for short 1-term stages).
// ---------------------------------------------------------------------------
#define GK 32
#define GROW 80
#define GSUB (128 * GROW)
#define G1STAGE (2 * GSUB)     // A|B = 20480
#define GNBUF 6
#define G1_DYN (GNBUF * G1STAGE + 256)   // 123136

__device__ __forceinline__ void gm1_load(
    uint32_t buf, const hf* ga, const hf* gb, int K, int tid)
{
    int row = tid >> 2, col = tid & 3;
    uint32_t so = (uint32_t)(row * GROW + col * 16);
    size_t g = (size_t)row * K + (size_t)col * 8;
    CP16(buf + so,        ga + g);
    CP16(buf + GSUB + so, gb + g);
}

__device__ __forceinline__ void g1_ldfr(uint32_t* fr, uint32_t sb,
                                        uint32_t a_off, uint32_t b_off, uint32_t ko)
{
    ldsm4(fr + 0,  sb + a_off + ko);
    ldsm4(fr + 4,  sb + a_off + 16u * GROW + ko);
    ldsm4(fr + 8,  sb + GSUB + b_off + ko);
    ldsm4(fr + 12, sb + GSUB + b_off + 16u * GROW + ko);
}

__device__ __forceinline__ void g1_mma(float acc[2][4][4], const uint32_t* fr)
{
    const uint32_t* a = fr;
    const uint32_t* b = fr + 8;
    #pragma unroll
    for (int i = 0; i < 2; i++)
        #pragma unroll
        for (int j = 0; j < 4; j++)
            mma16816(acc[i][j], a + i * 4, b + (j >> 1) * 4 + (j & 1) * 2);
}

// QKV GEMM: 1-term, fused scatter epilogue (q scaled, outputs fp16).
__global__ __launch_bounds__(512, 1) void gemm_qkv(
    const hf* __restrict__ A, const hf* __restrict__ B,
    const float* __restrict__ bias,
    hf* __restrict__ oqh, hf* __restrict__ okh, hf* __restrict__ ovh,
    int M, int N, int K)
{
    extern __shared__ __align__(128) char dynsm[];
    const uint32_t smbase = smem_u32(dynsm);

    const int tid = threadIdx.x;
    const int wid = tid >> 5, lane = tid & 31;
    const int wr = wid >> 2, wc = wid & 3;
    const int m0 = blockIdx.y * 128, n0 = blockIdx.x * 128;

    const hf* a0p = A + (size_t)m0 * K;
    const hf* b0p = B + (size_t)n0 * K;

    const uint32_t a_off = (uint32_t)((wr * 32 + (lane & 15)) * GROW + (lane >> 4) * 16);
    const uint32_t b_off = (uint32_t)((wc * 32 + (lane >> 4) * 8 + (lane & 7)) * GROW
                                      + (((lane & 15) >> 3) * 16));

    float acc[2][4][4];
    #pragma unroll
    for (int i = 0; i < 2; i++)
        #pragma unroll
        for (int j = 0; j < 4; j++)
            #pragma unroll
            for (int r = 0; r < 4; r++) acc[i][j][r] = 0.f;

    const int NS = K / GK;

    #pragma unroll
    for (int p = 0; p < 5; p++) {
        gm1_load(smbase + (uint32_t)p * G1STAGE,
                 a0p + (size_t)p * GK, b0p + (size_t)p * GK, K, tid);
        CP_COMMIT();
    }

    for (int s = 0; s < NS; s++) {
        CP_WAIT4();
        __syncthreads();

        const uint32_t sb = smbase + (uint32_t)(s % GNBUF) * G1STAGE;
        uint32_t f0[16], f1[16];
        g1_ldfr(f0, sb, a_off, b_off, 0);

        int t = s + 5;
        if (t < NS)
            gm1_load(smbase + (uint32_t)(t % GNBUF) * G1STAGE,
                     a0p + (size_t)t * GK, b0p + (size_t)t * GK, K, tid);
        CP_COMMIT();

        g1_ldfr(f1, sb, a_off, b_off, 32);
        g1_mma(acc, f0);
        g1_mma(acc, f1);
    }

    const int er = m0 + wr * 32 + (lane >> 2);
    const int ec = n0 + wc * 32 + 2 * (lane & 3);
    const int part = ec >> 10;
    // q scale folded in LOG2 domain: 1/sqrt(64) * log2(e)
    const float sc = (part == 0) ? 0.18033688f : 1.0f;
    hf* dst = (part == 0) ? oqh : ((part == 1) ? okh : ovh);
    #pragma unroll
    for (int i = 0; i < 2; i++)
        #pragma unroll
        for (int j = 0; j < 4; j++) {
            int r = er + i * 16, c = ec + j * 8;
            int hh = (c >> 6) & 15, d = c & 63;
            float b0 = bias[c], b1 = bias[c + 1];
            size_t off  = (((size_t)(r >> 11) * NHEAD + hh) * SEQ + (r & 2047)) * HDIM + d;
            int r2 = r + 8;
            size_t off2 = (((size_t)(r2 >> 11) * NHEAD + hh) * SEQ + (r2 & 2047)) * HDIM + d;
            *(uint32_t*)(dst + off)  = packhf((acc[i][j][0] + b0) * sc, (acc[i][j][1] + b1) * sc);
            *(uint32_t*)(dst + off2) = packhf((acc[i][j][2] + b0) * sc, (acc[i][j][3] + b1) * sc);
        }
}

// out-proj GEMM: 1-term, fp32 C.
__global__ __launch_bounds__(512, 1) void gemm_out(
    const hf* __restrict__ A, const hf* __restrict__ B, float* __restrict__ C,
    int M, int N, int K)
{
    extern __shared__ __align__(128) char dynsm[];
    const uint32_t smbase = smem_u32(dynsm);

    const int tid = threadIdx.x;
    const int wid = tid >> 5, lane = tid & 31;
    const int wr = wid >> 2, wc = wid & 3;
    const int m0 = blockIdx.y * 128, n0 = blockIdx.x * 128;

    const hf* a0p = A + (size_t)m0 * K;
    const hf* b0p = B + (size_t)n0 * K;

    const uint32_t a_off = (uint32_t)((wr * 32 + (lane & 15)) * GROW + (lane >> 4) * 16);
    const uint32_t b_off = (uint32_t)((wc * 32 + (lane >> 4) * 8 + (lane & 7)) * GROW
                                      + (((lane & 15) >> 3) * 16));

    float acc[2][4][4];
    #pragma unroll
    for (int i = 0; i < 2; i++)
        #pragma unroll
        for (int j = 0; j < 4; j++)
            #pragma unroll
            for (int r = 0; r < 4; r++) acc[i][j][r] = 0.f;

    const int NS = K / GK;

    #pragma unroll
    for (int p = 0; p < 5; p++) {
        gm1_load(smbase + (uint32_t)p * G1STAGE,
                 a0p + (size_t)p * GK, b0p + (size_t)p * GK, K, tid);
        CP_COMMIT();
    }

    for (int s = 0; s < NS; s++) {
        CP_WAIT4();
        __syncthreads();

        const uint32_t sb = smbase + (uint32_t)(s % GNBUF) * G1STAGE;
        uint32_t f0[16], f1[16];
        g1_ldfr(f0, sb, a_off, b_off, 0);

        int t = s + 5;
        if (t < NS)
            gm1_load(smbase + (uint32_t)(t % GNBUF) * G1STAGE,
                     a0p + (size_t)t * GK, b0p + (size_t)t * GK, K, tid);
        CP_COMMIT();

        g1_ldfr(f1, sb, a_off, b_off, 32);
        g1_mma(acc, f0);
        g1_mma(acc, f1);
    }

    const int er = m0 + wr * 32 + (lane >> 2);
    const int ec = n0 + wc * 32 + 2 * (lane & 3);
    #pragma unroll
    for (int i = 0; i < 2; i++)
        #pragma unroll
        for (int j = 0; j < 4; j++) {
            int r = er + i * 16, c = ec + j * 8;
            *(float2*)(C + (size_t)r * N + c) =
                make_float2(acc[i][j][0], acc[i][j][1]);
            *(float2*)(C + (size_t)(r + 8) * N + c) =
                make_float2(acc[i][j][2], acc[i][j][3]);
        }
}

// ---------------------------------------------------------------------------
// HMMA flash attention: Q, K, V, P all single fp16; ctx fp16.
// CTA = 128 q rows x one (b,h); 8 warps, warp = 16 q x 64 keys.
// ---------------------------------------------------------------------------
#define AROW 144
#define AQ_BYTES (128 * AROW)
#define AKV_BYTES (64 * AROW)
#define AST (2 * AKV_BYTES)
#define ATT_SMEM (AQ_BYTES + 3 * AST)   // 73728

__device__ __forceinline__ void att_load_kv(
    uint32_t base, const hf* khp, const hf* vhp, int kt, int tid)
{
    #pragma unroll
    for (int i = 0; i < 2; i++) {
        int c = i * 256 + tid;
        int row = c >> 3, col = c & 7;
        uint32_t so = (uint32_t)(row * AROW + col * 16);
        size_t g = (size_t)(kt * 64 + row) * HDIM + col * 8;
        CP16(base + so,             khp + g);
        CP16(base + AKV_BYTES + so, vhp + g);
    }
}

__device__ __forceinline__ void ld_kfr(uint32_t* f, uint32_t kvb, uint32_t kb_off, int ks)
{
    #pragma unroll
    for (int g = 0; g < 4; g++)
        ldsm4(f + g * 4, kvb + kb_off + (uint32_t)(g * 16 * AROW) + (uint32_t)(ks * 32));
}
__device__ __forceinline__ void ld_vfr(uint32_t* f, uint32_t kvb, uint32_t vb_off, int ks)
{
    #pragma unroll
    for (int g = 0; g < 4; g++)
        ldsm4t(f + g * 4, kvb + AKV_BYTES + vb_off
                        + (uint32_t)(ks * 16 * AROW) + (uint32_t)(g * 32));
}

__global__ __launch_bounds__(256) void flash_hmma(
    const hf* __restrict__ qh, const hf* __restrict__ kh,
    const hf* __restrict__ vh, hf* __restrict__ chi)
{
    extern __shared__ __align__(128) char asmbuf[];
    const uint32_t sb = smem_u32(asmbuf);
    const int tid = threadIdx.x, wid = tid >> 5, lane = tid & 31;
    const int qt = 15 - (int)blockIdx.x;
    const int h = blockIdx.y, b = blockIdx.z;
    const int q0 = qt * 128;
    const int ktmax = 2 * qt + 1;

    const size_t headoff = ((size_t)b * NHEAD + h) * SEQ * HDIM;
    const hf* qhp = qh + headoff + (size_t)q0 * HDIM;
    const hf* khp = kh + headoff;
    const hf* vhp = vh + headoff;

    #pragma unroll
    for (int i = 0; i < 4; i++) {
        int c = i * 256 + tid;
        int row = c >> 3, col = c & 7;
        uint32_t so = (uint32_t)(row * AROW + col * 16);
        size_t g = (size_t)row * HDIM + col * 8;
        CP16(sb + so, qhp + g);
    }
    att_load_kv(sb + AQ_BYTES, khp, vhp, 0, tid);
    CP_COMMIT();
    att_load_kv(sb + AQ_BYTES + AST, khp, vhp, 1, tid);
    CP_COMMIT();

    float s[8][4], acc[8][4];
    float m0v = -1e30f, m1v = -1e30f, l0v = 0.f, l1v = 0.f;
    #pragma unroll
    for (int nc = 0; nc < 8; nc++) {
        acc[nc][0] = acc[nc][1] = acc[nc][2] = acc[nc][3] = 0.f;
    }
    uint32_t qf[16];

    const uint32_t a_off = (uint32_t)((wid * 16 + (lane & 15)) * AROW + (lane >> 4) * 16);
    const uint32_t kb_off = (uint32_t)(((lane >> 4) * 8 + (lane & 7)) * AROW
                                       + (((lane & 15) >> 3) * 16));
    const uint32_t vb_off = (uint32_t)((lane & 15) * AROW + (lane >> 4) * 16);

    for (int kt = 0; kt <= ktmax; kt++) {
        if (kt < ktmax) { CP_WAIT1(); } else { CP_WAIT0(); }
        __syncthreads();

        if (kt == 0) {
            #pragma unroll
            for (int ks = 0; ks < 4; ks++)
                ldsm4(&qf[ks * 4], sb + a_off + (uint32_t)(ks * 32));
        }
        int t = kt + 2;
        if (t <= ktmax) {
            att_load_kv(sb + AQ_BYTES + (uint32_t)(t % 3) * AST, khp, vhp, t, tid);
            CP_COMMIT();
        }
        const uint32_t kvb = sb + AQ_BYTES + (uint32_t)(kt % 3) * AST;

        // ---- scores = Q K^T (1-term) ----
        #pragma unroll
        for (int nc = 0; nc < 8; nc++) {
            s[nc][0] = s[nc][1] = s[nc][2] = s[nc][3] = 0.f;
        }
        {
            uint32_t kfb[2][16];
            ld_kfr(kfb[0], kvb, kb_off, 0);
            #pragma unroll
            for (int ks = 0; ks < 4; ks++) {
                if (ks < 3) ld_kfr(kfb[(ks + 1) & 1], kvb, kb_off, ks + 1);
                const uint32_t* kf = kfb[ks & 1];
                #pragma unroll
                for (int nc = 0; nc < 8; nc++)
                    mma16816(s[nc], &qf[ks * 4], kf + (nc >> 1) * 4 + (nc & 1) * 2);
            }
        }

        // ---- online softmax (log2 domain; q pre-scaled by log2e/8) ----
        if (kt >= 2 * qt) {
            const int keyb = kt * 64 + 2 * (lane & 3);
            const int r0 = q0 + wid * 16 + (lane >> 2);
            #pragma unroll
            for (int nc = 0; nc < 8; nc++) {
                int k0 = keyb + nc * 8;
                if (k0     > r0)     s[nc][0] = -1e30f;
                if (k0 + 1 > r0)     s[nc][1] = -1e30f;
                if (k0     > r0 + 8) s[nc][2] = -1e30f;
                if (k0 + 1 > r0 + 8) s[nc][3] = -1e30f;
            }
        }
        float mx0 = -1e30f, mx1 = -1e30f;
        #pragma unroll
        for (int nc = 0; nc < 8; nc++) {
            mx0 = fmaxf(mx0, fmaxf(s[nc][0], s[nc][1]));
            mx1 = fmaxf(mx1, fmaxf(s[nc][2], s[nc][3]));
        }
        mx0 = fmaxf(mx0, __shfl_xor_sync(0xffffffffu, mx0, 1));
        mx0 = fmaxf(mx0, __shfl_xor_sync(0xffffffffu, mx0, 2));
        mx1 = fmaxf(mx1, __shfl_xor_sync(0xffffffffu, mx1, 1));
        mx1 = fmaxf(mx1, __shfl_xor_sync(0xffffffffu, mx1, 2));
        float mn0 = fmaxf(m0v, mx0), mn1 = fmaxf(m1v, mx1);
        float c0 = ex2(m0v - mn0), c1 = ex2(m1v - mn1);
        float su0 = 0.f, su1 = 0.f;
        #pragma unroll
        for (int nc = 0; nc < 8; nc++) {
            s[nc][0] = ex2(s[nc][0] - mn0);
            s[nc][1] = ex2(s[nc][1] - mn0);
            s[nc][2] = ex2(s[nc][2] - mn1);
            s[nc][3] = ex2(s[nc][3] - mn1);
            su0 += s[nc][0] + s[nc][1];
            su1 += s[nc][2] + s[nc][3];
        }
        su0 += __shfl_xor_sync(0xffffffffu, su0, 1);
        su0 += __shfl_xor_sync(0xffffffffu, su0, 2);
        su1 += __shfl_xor_sync(0xffffffffu, su1, 1);
        su1 += __shfl_xor_sync(0xffffffffu, su1, 2);
        l0v = l0v * c0 + su0;
        l1v = l1v * c1 + su1;
        m0v = mn0; m1v = mn1;
        #pragma unroll
        for (int nc = 0; nc < 8; nc++) {
            acc[nc][0] *= c0; acc[nc][1] *= c0;
            acc[nc][2] *= c1; acc[nc][3] *= c1;
        }

        // ---- ctx += P V (1-term: P single fp16) ----
        {
            uint32_t vfb[2][16];
            ld_vfr(vfb[0], kvb, vb_off, 0);
            #pragma unroll
            for (int ks = 0; ks < 4; ks++) {
                if (ks < 3) ld_vfr(vfb[(ks + 1) & 1], kvb, vb_off, ks + 1);
                uint32_t ph[4];
                ph[0] = packhf(s[2 * ks][0],     s[2 * ks][1]);
                ph[1] = packhf(s[2 * ks][2],     s[2 * ks][3]);
                ph[2] = packhf(s[2 * ks + 1][0], s[2 * ks + 1][1]);
                ph[3] = packhf(s[2 * ks + 1][2], s[2 * ks + 1][3]);
                const uint32_t* vf = vfb[ks & 1];
                #pragma unroll
                for (int nc = 0; nc < 8; nc++)
                    mma16816(acc[nc], ph, vf + (nc >> 1) * 4 + (nc & 1) * 2);
            }
        }
    }

    float i0 = 1.f / l0v, i1 = 1.f / l1v;
    const int r0 = q0 + wid * 16 + (lane >> 2);
    const int cb = h * HDIM + 2 * (lane & 3);
    #pragma unroll
    for (int nc = 0; nc < 8; nc++) {
        int cc = cb + nc * 8;
        size_t off = (size_t)(b * SEQ + r0) * DMODEL + cc;
        *(uint32_t*)(chi + off) = packhf(acc[nc][0] * i0, acc[nc][1] * i0);
        off = (size_t)(b * SEQ + r0 + 8) * DMODEL + cc;
        *(uint32_t*)(chi + off) = packhf(acc[nc][2] * i1, acc[nc][3] * i1);
    }
}

// ---------------------------------------------------------------------------
extern "C" void kernel_launch(void* const* d_in, const int* in_sizes, int n_in,
                              void* d_out, int out_size)
{
    (void)in_sizes; (void)n_in; (void)out_size;
    const float* x     = (const float*)d_in[0];
    const float* W_qkv = (const float*)d_in[1];
    const float* b_qkv = (const float*)d_in[2];
    const float* W_out = (const float*)d_in[3];
    float* out = (float*)d_out;

    hf *xh, *wqh, *woh, *chi, *qh, *kh, *vh;
    cudaGetSymbolAddress((void**)&xh, g_xh);
    cudaGetSymbolAddress((void**)&wqh, g_wqh);
    cudaGetSymbolAddress((void**)&woh, g_woh);
    cudaGetSymbolAddress((void**)&chi, g_chi);
    cudaGetSymbolAddress((void**)&qh, g_qh);
    cudaGetSymbolAddress((void**)&kh, g_kh);
    cudaGetSymbolAddress((void**)&vh, g_vh);

    cudaFuncSetAttribute(gemm_qkv, cudaFuncAttributeMaxDynamicSharedMemorySize, G1_DYN);
    cudaFuncSetAttribute(gemm_out, cudaFuncAttributeMaxDynamicSharedMemorySize, G1_DYN);
    cudaFuncSetAttribute(flash_hmma, cudaFuncAttributeMaxDynamicSharedMemorySize, ATT_SMEM);

    // fused pre-pass (one launch)
    prep_kernel<<<8192, 256>>>(x, W_qkv, W_out, xh, wqh, woh);

    gemm_qkv<<<dim3(QKV_N / 128, ROWS / 128), 512, G1_DYN>>>(
        xh, wqh, b_qkv, qh, kh, vh, ROWS, QKV_N, DMODEL);

    flash_hmma<<<dim3(16, NHEAD, BATCH), 256, ATT_SMEM>>>(
        qh, kh, vh, chi);

    gemm_out<<<dim3(DMODEL / 128, ROWS / 128), 512, G1_DYN>>>(
        chi, woh, out, ROWS, DMODEL, DMODEL);
}